// round 4
// baseline (speedup 1.0000x reference)
#include <cuda_runtime.h>
#include <cstdint>

#define S_LEN   2048
#define DMODEL  2048
#define NH      16
#define HDIM    128
#define KV_DM   512
#define NQT16   16
#define HEAVY   204
#define RECENT  204
#define SEL     (S_LEN - RECENT)    // 1844
#define MASKW   (S_LEN + 1)         // 2049

__device__ float g_hid[S_LEN * DMODEL];
__device__ float g_qw[DMODEL * DMODEL];
__device__ float g_kw[DMODEL * KV_DM];
__device__ float g_vw[DMODEL * KV_DM];
__device__ float g_ow[DMODEL * DMODEL];
__device__ float g_q[S_LEN * DMODEL];
__device__ float g_k[S_LEN * KV_DM];
__device__ float g_v[S_LEN * KV_DM];
__device__ float g_ctx[S_LEN * DMODEL];
__device__ float g_colpart[NH * NQT16 * S_LEN];

// ---------------------------------------------------------------------------
__device__ __forceinline__ float tf32r(float x) {
    uint32_t u;
    asm("cvt.rna.tf32.f32 %0, %1;" : "=r"(u) : "f"(x));
    return __uint_as_float(u);
}
__device__ __forceinline__ float ex2f(float x) {
    float y;
    asm("ex2.approx.ftz.f32 %0, %1;" : "=f"(y) : "f"(x));
    return y;
}
__device__ __forceinline__ void mma_tf32(float* c, const uint32_t* a, const uint32_t* b) {
    asm volatile(
        "mma.sync.aligned.m16n8k8.row.col.f32.tf32.tf32.f32 "
        "{%0,%1,%2,%3}, {%4,%5,%6,%7}, {%8,%9}, {%0,%1,%2,%3};"
        : "+f"(c[0]), "+f"(c[1]), "+f"(c[2]), "+f"(c[3])
        : "r"(a[0]), "r"(a[1]), "r"(a[2]), "r"(a[3]), "r"(b[0]), "r"(b[1]));
}
__device__ __forceinline__ void cpa16(uint32_t s, const float* g) {
    asm volatile("cp.async.cg.shared.global [%0], [%1], 16;" :: "r"(s), "l"(g));
}
__device__ __forceinline__ void cp_commit() {
    asm volatile("cp.async.commit_group;");
}
template<int N> __device__ __forceinline__ void cp_wait() {
    asm volatile("cp.async.wait_group %0;" :: "n"(N));
}
__device__ __forceinline__ unsigned encf(float x) {
    unsigned b = __float_as_uint(x);
    return (b & 0x80000000u) ? ~b : (b | 0x80000000u);
}

__global__ void zero_kernel(float* p, int n) {
    int i = blockIdx.x * 256 + threadIdx.x;
    if (i < n) p[i] = 0.0f;
}
__global__ void round4_kernel(float4* dst, const float4* src, int n4) {
    int i = blockIdx.x * 256 + threadIdx.x;
    if (i < n4) {
        float4 v = src[i];
        dst[i] = make_float4(tf32r(v.x), tf32r(v.y), tf32r(v.z), tf32r(v.w));
    }
}

// ---------------------------------------------------------------------------
// cp.async double-buffered tf32 GEMM (same as R3). BM=128, BK=16, K=2048.
// ---------------------------------------------------------------------------
template<int BN, int WM, int WN, bool ROUND, bool HASBIAS>
__global__ __launch_bounds__(256) void gemm_ca(
    const float* __restrict__ A,
    const float* __restrict__ B0, const float* __restrict__ B1,
    const float* __restrict__ bias0, const float* __restrict__ bias1,
    float* __restrict__ C0, float* __restrict__ C1, int N)
{
    constexpr int BM = 128, BK = 16, KD = 2048;
    constexpr int ASS = 20;
    constexpr int BSS = BN + 4;
    constexpr int MI = WM / 16, NJ = WN / 8;
    constexpr int WARPS_M = BM / WM;
    constexpr int NIT = KD / BK;

    __shared__ float As[2][BM * ASS];
    __shared__ float Bs[2][BK * BSS];

    const int tid = threadIdx.x;
    const int lane = tid & 31, w = tid >> 5;
    const int wm0 = (w % WARPS_M) * WM;
    const int wn0 = (w / WARPS_M) * WN;
    const int bm = blockIdx.y * BM;
    const int bn = blockIdx.x * BN;

    const float* Bm  = (blockIdx.z == 0) ? B0 : B1;
    const float* bia = (blockIdx.z == 0) ? bias0 : bias1;
    float* C         = (blockIdx.z == 0) ? C0 : C1;

    const int ara = tid & 127;
    const int aca = (tid >> 7) * 8;
    const uint32_t sA = (uint32_t)__cvta_generic_to_shared(&As[0][0]);
    const uint32_t sB = (uint32_t)__cvta_generic_to_shared(&Bs[0][0]);

    float acc[MI][NJ][4];
#pragma unroll
    for (int mi = 0; mi < MI; mi++)
#pragma unroll
        for (int nj = 0; nj < NJ; nj++)
#pragma unroll
            for (int c = 0; c < 4; c++) acc[mi][nj][c] = 0.0f;

    auto issue = [&](int st, int k0) {
        const float* ga = &A[(size_t)(bm + ara) * KD + k0 + aca];
        uint32_t sa = sA + (uint32_t)((st * BM + ara) * ASS + aca) * 4u;
        cpa16(sa, ga);
        cpa16(sa + 16, ga + 4);
        if (BN == 128) {
            const int rb = tid >> 5;
            const int cb = (tid & 31) * 4;
            const float* gb = &Bm[(size_t)(k0 + rb) * N + bn + cb];
            uint32_t sb = sB + (uint32_t)((st * BK + rb) * BSS + cb) * 4u;
            cpa16(sb, gb);
            cpa16(sb + (uint32_t)(8 * BSS) * 4u, gb + (size_t)8 * N);
        } else {
            const int rb = tid >> 4;
            const int cb = (tid & 15) * 4;
            const float* gb = &Bm[(size_t)(k0 + rb) * N + bn + cb];
            uint32_t sb = sB + (uint32_t)((st * BK + rb) * BSS + cb) * 4u;
            cpa16(sb, gb);
        }
    };

    issue(0, 0);
    cp_commit();

    for (int it = 0; it < NIT; it++) {
        if (it + 1 < NIT) {
            issue((it + 1) & 1, (it + 1) * BK);
            cp_commit();
            cp_wait<1>();
        } else {
            cp_wait<0>();
        }
        __syncthreads();
        const float* as = &As[it & 1][0];
        const float* bs = &Bs[it & 1][0];
#pragma unroll
        for (int ks = 0; ks < 2; ks++) {
            const int kk = ks * 8;
            uint32_t af[MI][4], bf[NJ][2];
#pragma unroll
            for (int mi = 0; mi < MI; mi++) {
                int m0 = wm0 + 16 * mi + (lane >> 2);
                af[mi][0] = __float_as_uint(as[m0 * ASS + kk + (lane & 3)]);
                af[mi][1] = __float_as_uint(as[(m0 + 8) * ASS + kk + (lane & 3)]);
                af[mi][2] = __float_as_uint(as[m0 * ASS + kk + 4 + (lane & 3)]);
                af[mi][3] = __float_as_uint(as[(m0 + 8) * ASS + kk + 4 + (lane & 3)]);
            }
#pragma unroll
            for (int nj = 0; nj < NJ; nj++) {
                int n0 = wn0 + 8 * nj + (lane >> 2);
                bf[nj][0] = __float_as_uint(bs[(kk + (lane & 3)) * BSS + n0]);
                bf[nj][1] = __float_as_uint(bs[(kk + 4 + (lane & 3)) * BSS + n0]);
            }
#pragma unroll
            for (int mi = 0; mi < MI; mi++)
#pragma unroll
                for (int nj = 0; nj < NJ; nj++)
                    mma_tf32(acc[mi][nj], af[mi], bf[nj]);
        }
        __syncthreads();
    }

#pragma unroll
    for (int mi = 0; mi < MI; mi++) {
#pragma unroll
        for (int nj = 0; nj < NJ; nj++) {
            int row = bm + wm0 + 16 * mi + (lane >> 2);
            int col = bn + wn0 + 8 * nj + 2 * (lane & 3);
            float bx = 0.0f, by = 0.0f;
            if (HASBIAS) { bx = bia[col]; by = bia[col + 1]; }
            float v0x = acc[mi][nj][0] + bx, v0y = acc[mi][nj][1] + by;
            float v1x = acc[mi][nj][2] + bx, v1y = acc[mi][nj][3] + by;
            if (ROUND) {
                v0x = tf32r(v0x); v0y = tf32r(v0y);
                v1x = tf32r(v1x); v1y = tf32r(v1y);
            }
            *(float2*)&C[(size_t)row * N + col] = make_float2(v0x, v0y);
            *(float2*)&C[(size_t)(row + 8) * N + col] = make_float2(v1x, v1y);
        }
    }
}

// ---------------------------------------------------------------------------
// Fused flash attention. One block per (qt128, h). 512 threads, 16 warps.
// Pass A: l = sum 2^(s*c) (no max; scores bounded). Pass B: recompute QK,
// p = 2^(s*c)/l -> colsums + P@V tensor MMA. No score HBM traffic.
// smem (floats): Qs[128*132] Ks[64*132] Vs[64*136] sPt[128*68] red[512] il[128]
// ---------------------------------------------------------------------------
#define QS_OFF   0
#define KS_OFF   16896
#define VS_OFF   25344
#define PT_OFF   34048
#define RED_OFF  42752
#define IL_OFF   43264
#define ATTN_SMEM ((43264 + 128) * 4)

__global__ __launch_bounds__(512, 1) void attn_fused() {
    extern __shared__ float smem[];
    float* Qs  = smem + QS_OFF;
    float* Ks  = smem + KS_OFF;
    float* Vs  = smem + VS_OFF;
    float* sPt = smem + PT_OFF;
    float* red = smem + RED_OFF;
    float* il  = smem + IL_OFF;

    const int qt = 15 - blockIdx.x;      // heavy blocks first
    const int h  = blockIdx.y;
    const int kvh = h >> 2;
    const int qbase = qt * 128;
    const int tid = threadIdx.x;
    const int lane = tid & 31, w = tid >> 5;
    const int wm  = (w & 3) * 32;        // q-row offset of this warp
    const int wn  = (w >> 2) * 16;       // QK: 16 key-cols per warp
    const int wn2 = (w >> 2) * 32;       // PV: 32 out-cols per warp
    const float SCL2 = 0.08838834764831845f * 1.4426950408889634f;

    // load Q tile (tf32-rounded already)
    {
        int r = tid >> 2, cb = (tid & 3) * 32;
        const float* qp = &g_q[(size_t)(qbase + r) * DMODEL + h * HDIM + cb];
#pragma unroll
        for (int i = 0; i < 8; i++)
            *(float4*)&Qs[r * 132 + cb + 4 * i] = *(const float4*)&qp[4 * i];
    }

    const int nkt = 2 * qt + 2;
    float lp[4] = {0.f, 0.f, 0.f, 0.f};

    // ------------------------------- PASS A -------------------------------
    for (int kt = 0; kt < nkt; kt++) {
        __syncthreads();
        {
            int r = tid >> 3, cb = (tid & 7) * 16;
            const float* kp = &g_k[(size_t)(kt * 64 + r) * KV_DM + kvh * HDIM + cb];
#pragma unroll
            for (int i = 0; i < 4; i++)
                *(float4*)&Ks[r * 132 + cb + 4 * i] = *(const float4*)&kp[4 * i];
        }
        __syncthreads();

        float sacc[2][2][4];
#pragma unroll
        for (int mi = 0; mi < 2; mi++)
#pragma unroll
            for (int nj = 0; nj < 2; nj++)
#pragma unroll
                for (int c = 0; c < 4; c++) sacc[mi][nj][c] = 0.0f;

#pragma unroll
        for (int ks = 0; ks < 16; ks++) {
            const int kk = ks * 8;
            uint32_t af[2][4], bf[2][2];
#pragma unroll
            for (int mi = 0; mi < 2; mi++) {
                int m0 = wm + 16 * mi + (lane >> 2);
                af[mi][0] = __float_as_uint(Qs[m0 * 132 + kk + (lane & 3)]);
                af[mi][1] = __float_as_uint(Qs[(m0 + 8) * 132 + kk + (lane & 3)]);
                af[mi][2] = __float_as_uint(Qs[m0 * 132 + kk + 4 + (lane & 3)]);
                af[mi][3] = __float_as_uint(Qs[(m0 + 8) * 132 + kk + 4 + (lane & 3)]);
            }
#pragma unroll
            for (int nj = 0; nj < 2; nj++) {
                int n0 = wn + 8 * nj + (lane >> 2);
                bf[nj][0] = __float_as_uint(Ks[n0 * 132 + kk + (lane & 3)]);
                bf[nj][1] = __float_as_uint(Ks[n0 * 132 + kk + 4 + (lane & 3)]);
            }
#pragma unroll
            for (int mi = 0; mi < 2; mi++)
#pragma unroll
                for (int nj = 0; nj < 2; nj++)
                    mma_tf32(sacc[mi][nj], af[mi], bf[nj]);
        }

        const bool diag = (kt >= 2 * qt);
#pragma unroll
        for (int mi = 0; mi < 2; mi++) {
            int grow = qbase + wm + 16 * mi + (lane >> 2);
#pragma unroll
            for (int nj = 0; nj < 2; nj++) {
                int col = kt * 64 + wn + 8 * nj + 2 * (lane & 3);
                float e0 = (!diag || col     <= grow)     ? ex2f(sacc[mi][nj][0] * SCL2) : 0.f;
                float e1 = (!diag || col + 1 <= grow)     ? ex2f(sacc[mi][nj][1] * SCL2) : 0.f;
                float e2 = (!diag || col     <= grow + 8) ? ex2f(sacc[mi][nj][2] * SCL2) : 0.f;
                float e3 = (!diag || col + 1 <= grow + 8) ? ex2f(sacc[mi][nj][3] * SCL2) : 0.f;
                lp[mi * 2 + 0] += e0 + e1;
                lp[mi * 2 + 1] += e2 + e3;
            }
        }
    }

    // reduce l: quad shuffle, then across 4 n-warp groups via smem
#pragma unroll
    for (int i = 0; i < 4; i++) {
        lp[i] += __shfl_xor_sync(0xFFFFFFFFu, lp[i], 1);
        lp[i] += __shfl_xor_sync(0xFFFFFFFFu, lp[i], 2);
    }
    __syncthreads();
    if ((lane & 3) == 0) {
        int wg = w >> 2;
#pragma unroll
        for (int mi = 0; mi < 2; mi++) {
            red[(wm + 16 * mi + (lane >> 2)) * 4 + wg]     = lp[mi * 2 + 0];
            red[(wm + 16 * mi + 8 + (lane >> 2)) * 4 + wg] = lp[mi * 2 + 1];
        }
    }
    __syncthreads();
    if (tid < 128)
        il[tid] = 1.0f / (red[tid * 4] + red[tid * 4 + 1] + red[tid * 4 + 2] + red[tid * 4 + 3]);
    __syncthreads();

    float ilv[4];
#pragma unroll
    for (int mi = 0; mi < 2; mi++) {
        ilv[mi * 2 + 0] = il[wm + 16 * mi + (lane >> 2)];
        ilv[mi * 2 + 1] = il[wm + 16 * mi + 8 + (lane >> 2)];
    }

    // ------------------------------- PASS B -------------------------------
    float o[2][4][4];
#pragma unroll
    for (int mi = 0; mi < 2; mi++)
#pragma unroll
        for (int nj = 0; nj < 4; nj++)
#pragma unroll
            for (int c = 0; c < 4; c++) o[mi][nj][c] = 0.0f;

    for (int kt = 0; kt < nkt; kt++) {
        __syncthreads();
        {
            int r = tid >> 3, cb = (tid & 7) * 16;
            const float* kp = &g_k[(size_t)(kt * 64 + r) * KV_DM + kvh * HDIM + cb];
            const float* vp = &g_v[(size_t)(kt * 64 + r) * KV_DM + kvh * HDIM + cb];
#pragma unroll
            for (int i = 0; i < 4; i++) {
                *(float4*)&Ks[r * 132 + cb + 4 * i] = *(const float4*)&kp[4 * i];
                *(float4*)&Vs[r * 136 + cb + 4 * i] = *(const float4*)&vp[4 * i];
            }
        }
        __syncthreads();

        float sacc[2][2][4];
#pragma unroll
        for (int mi = 0; mi < 2; mi++)
#pragma unroll
            for (int nj = 0; nj < 2; nj++)
#pragma unroll
                for (int c = 0; c < 4; c++) sacc[mi][nj][c] = 0.0f;

#pragma unroll
        for (int ks = 0; ks < 16; ks++) {
            const int kk = ks * 8;
            uint32_t af[2][4], bf[2][2];
#pragma unroll
            for (int mi = 0; mi < 2; mi++) {
                int m0 = wm + 16 * mi + (lane >> 2);
                af[mi][0] = __float_as_uint(Qs[m0 * 132 + kk + (lane & 3)]);
                af[mi][1] = __float_as_uint(Qs[(m0 + 8) * 132 + kk + (lane & 3)]);
                af[mi][2] = __float_as_uint(Qs[m0 * 132 + kk + 4 + (lane & 3)]);
                af[mi][3] = __float_as_uint(Qs[(m0 + 8) * 132 + kk + 4 + (lane & 3)]);
            }
#pragma unroll
            for (int nj = 0; nj < 2; nj++) {
                int n0 = wn + 8 * nj + (lane >> 2);
                bf[nj][0] = __float_as_uint(Ks[n0 * 132 + kk + (lane & 3)]);
                bf[nj][1] = __float_as_uint(Ks[n0 * 132 + kk + 4 + (lane & 3)]);
            }
#pragma unroll
            for (int mi = 0; mi < 2; mi++)
#pragma unroll
                for (int nj = 0; nj < 2; nj++)
                    mma_tf32(sacc[mi][nj], af[mi], bf[nj]);
        }

        const bool diag = (kt >= 2 * qt);
#pragma unroll
        for (int mi = 0; mi < 2; mi++) {
            int rl = wm + 16 * mi + (lane >> 2);
            int grow = qbase + rl;
#pragma unroll
            for (int nj = 0; nj < 2; nj++) {
                int cl = wn + 8 * nj + 2 * (lane & 3);
                int col = kt * 64 + cl;
                float p0 = (!diag || col     <= grow)     ? ex2f(sacc[mi][nj][0] * SCL2) * ilv[mi * 2]     : 0.f;
                float p1 = (!diag || col + 1 <= grow)     ? ex2f(sacc[mi][nj][1] * SCL2) * ilv[mi * 2]     : 0.f;
                float p2 = (!diag || col     <= grow + 8) ? ex2f(sacc[mi][nj][2] * SCL2) * ilv[mi * 2 + 1] : 0.f;
                float p3 = (!diag || col + 1 <= grow + 8) ? ex2f(sacc[mi][nj][3] * SCL2) * ilv[mi * 2 + 1] : 0.f;
                *(float2*)&sPt[rl * 68 + cl]       = make_float2(p0, p1);
                *(float2*)&sPt[(rl + 8) * 68 + cl] = make_float2(p2, p3);
            }
        }
        __syncthreads();

        // colsum partials (deterministic, fixed split)
        if (tid < 256) {
            int c = tid & 63, seg = tid >> 6;
            float cs = 0.0f;
#pragma unroll 8
            for (int r = 0; r < 32; r++) cs += sPt[(seg * 32 + r) * 68 + c];
            red[c * 4 + seg] = cs;
        }

        // P@V
#pragma unroll
        for (int ks = 0; ks < 8; ks++) {
            const int kk = ks * 8;
            uint32_t af[2][4], bf[4][2];
#pragma unroll
            for (int mi = 0; mi < 2; mi++) {
                int m0 = wm + 16 * mi + (lane >> 2);
                af[mi][0] = __float_as_uint(sPt[m0 * 68 + kk + (lane & 3)]);
                af[mi][1] = __float_as_uint(sPt[(m0 + 8) * 68 + kk + (lane & 3)]);
                af[mi][2] = __float_as_uint(sPt[m0 * 68 + kk + 4 + (lane & 3)]);
                af[mi][3] = __float_as_uint(sPt[(m0 + 8) * 68 + kk + 4 + (lane & 3)]);
            }
#pragma unroll
            for (int nj = 0; nj < 4; nj++) {
                int n0 = wn2 + 8 * nj + (lane >> 2);
                bf[nj][0] = __float_as_uint(Vs[(kk + (lane & 3)) * 136 + n0]);
                bf[nj][1] = __float_as_uint(Vs[(kk + 4 + (lane & 3)) * 136 + n0]);
            }
#pragma unroll
            for (int mi = 0; mi < 2; mi++)
#pragma unroll
                for (int nj = 0; nj < 4; nj++)
                    mma_tf32(o[mi][nj], af[mi], bf[nj]);
        }
        __syncthreads();
        if (tid < 64)
            g_colpart[((size_t)h * NQT16 + qt) * S_LEN + kt * 64 + tid] =
                red[tid * 4] + red[tid * 4 + 1] + red[tid * 4 + 2] + red[tid * 4 + 3];
    }

    // write context
#pragma unroll
    for (int mi = 0; mi < 2; mi++)
#pragma unroll
        for (int nj = 0; nj < 4; nj++) {
            int row = qbase + wm + 16 * mi + (lane >> 2);
            int col = h * HDIM + wn2 + 8 * nj + 2 * (lane & 3);
            *(float2*)&g_ctx[(size_t)row * DMODEL + col] =
                make_float2(tf32r(o[mi][nj][0]), tf32r(o[mi][nj][1]));
            *(float2*)&g_ctx[(size_t)(row + 8) * DMODEL + col] =
                make_float2(tf32r(o[mi][nj][2]), tf32r(o[mi][nj][3]));
        }
}

// ---------------------------------------------------------------------------
// Heavy-hitter mask via bitonic sort of composite keys (exact jax.lax.top_k
// semantics: value desc, lowest index on ties).
// ---------------------------------------------------------------------------
__global__ __launch_bounds__(1024) void topk_kernel(float* __restrict__ mask_out) {
    const int h = blockIdx.x;
    const int tid = threadIdx.x;
    __shared__ unsigned long long keys[2048];

    for (int i = tid; i < 2048; i += 1024) {
        unsigned ev = 0u;
        if (i < SEL) {
            float s = 0.0f;
#pragma unroll
            for (int qt = 0; qt < NQT16; qt++)
                s += g_colpart[((size_t)h * NQT16 + qt) * S_LEN + i];
            ev = encf(s);
        }
        keys[i] = ((unsigned long long)ev << 32) | (unsigned)(2047 - i);
    }
    float* mrow = mask_out + (size_t)h * MASKW;
    for (int i = tid; i < MASKW; i += 1024)
        mrow[i] = (i >= (MASKW - RECENT)) ? 1.0f : 0.0f;
    __syncthreads();

    // ascending bitonic sort; take the 204 largest from the tail
    for (int k = 2; k <= 2048; k <<= 1) {
        for (int j = k >> 1; j > 0; j >>= 1) {
            for (int idx = tid; idx < 2048; idx += 1024) {
                int ixj = idx ^ j;
                if (ixj > idx) {
                    unsigned long long a = keys[idx], b = keys[ixj];
                    bool up = (idx & k) == 0;
                    if (up ? (a > b) : (a < b)) { keys[idx] = b; keys[ixj] = a; }
                }
            }
            __syncthreads();
        }
    }
    for (int i = 2048 - HEAVY + tid; i < 2048; i += 1024) {
        int idx = 2047 - (int)(keys[i] & 0xFFFFFFFFu);
        mrow[idx] = 1.0f;
    }
}

// ---------------------------------------------------------------------------
extern "C" void kernel_launch(void* const* d_in, const int* in_sizes, int n_in,
                              void* d_out, int out_size) {
    (void)in_sizes; (void)n_in; (void)out_size;
    const float* hidden = (const float*)d_in[0];
    const float* q_w = (const float*)d_in[1];
    const float* q_b = (const float*)d_in[2];
    const float* k_w = (const float*)d_in[3];
    const float* k_b = (const float*)d_in[4];
    const float* v_w = (const float*)d_in[5];
    const float* v_b = (const float*)d_in[6];
    const float* o_w = (const float*)d_in[7];
    float* out = (float*)d_out;

    static bool attr_set = false;
    if (!attr_set) {
        cudaFuncSetAttribute(attn_fused, cudaFuncAttributeMaxDynamicSharedMemorySize, ATTN_SMEM);
        attr_set = true;
    }

    float *ghid, *gqw, *gkw, *gvw, *gow, *gq, *gk, *gv, *gctx, *gcp;
    cudaGetSymbolAddress((void**)&ghid, g_hid);
    cudaGetSymbolAddress((void**)&gqw,  g_qw);
    cudaGetSymbolAddress((void**)&gkw,  g_kw);
    cudaGetSymbolAddress((void**)&gvw,  g_vw);
    cudaGetSymbolAddress((void**)&gow,  g_ow);
    cudaGetSymbolAddress((void**)&gq,   g_q);
    cudaGetSymbolAddress((void**)&gk,   g_k);
    cudaGetSymbolAddress((void**)&gv,   g_v);
    cudaGetSymbolAddress((void**)&gctx, g_ctx);
    cudaGetSymbolAddress((void**)&gcp,  g_colpart);

    round4_kernel<<<(S_LEN * DMODEL / 4 + 255) / 256, 256>>>((float4*)ghid, (const float4*)hidden, S_LEN * DMODEL / 4);
    round4_kernel<<<(DMODEL * DMODEL / 4 + 255) / 256, 256>>>((float4*)gqw, (const float4*)q_w, DMODEL * DMODEL / 4);
    round4_kernel<<<(DMODEL * KV_DM / 4 + 255) / 256, 256>>>((float4*)gkw, (const float4*)k_w, DMODEL * KV_DM / 4);
    round4_kernel<<<(DMODEL * KV_DM / 4 + 255) / 256, 256>>>((float4*)gvw, (const float4*)v_w, DMODEL * KV_DM / 4);
    round4_kernel<<<(DMODEL * DMODEL / 4 + 255) / 256, 256>>>((float4*)gow, (const float4*)o_w, DMODEL * DMODEL / 4);

    const int ncp = NH * NQT16 * S_LEN;
    zero_kernel<<<(ncp + 255) / 256, 256>>>(gcp, ncp);

    gemm_ca<128, 64, 32, true, true><<<dim3(DMODEL / 128, S_LEN / 128, 1), 256>>>(
        ghid, gqw, nullptr, q_b, nullptr, gq, nullptr, DMODEL);
    gemm_ca<64, 32, 32, true, true><<<dim3(KV_DM / 64, S_LEN / 128, 2), 256>>>(
        ghid, gkw, gvw, k_b, v_b, gk, gv, KV_DM);

    attn_fused<<<dim3(16, NH), 512, ATTN_SMEM>>>();

    topk_kernel<<<NH, 1024>>>(out + (size_t)S_LEN * DMODEL);

    gemm_ca<128, 64, 32, false, false><<<dim3(DMODEL / 128, S_LEN / 128, 1), 256>>>(
        gctx, gow, nullptr, nullptr, nullptr, out, nullptr, DMODEL);
}

// round 5
// speedup vs baseline: 1.1322x; 1.1322x over previous
#include <cuda_runtime.h>
#include <cstdint>

#define S_LEN   2048
#define DMODEL  2048
#define NH      16
#define HDIM    128
#define KV_DM   512
#define NQT16   16
#define HEAVY   204
#define RECENT  204
#define SEL     (S_LEN - RECENT)    // 1844
#define MASKW   (S_LEN + 1)         // 2049

__device__ float g_hid[S_LEN * DMODEL];
__device__ float g_qwT[DMODEL * DMODEL];   // [n][k]
__device__ float g_kwT[KV_DM * DMODEL];
__device__ float g_vwT[KV_DM * DMODEL];
__device__ float g_owT[DMODEL * DMODEL];
__device__ float g_q[S_LEN * DMODEL];
__device__ float g_k[S_LEN * KV_DM];
__device__ float g_v[S_LEN * KV_DM];
__device__ float g_ctx[S_LEN * DMODEL];
__device__ float g_colpart[NH * NQT16 * S_LEN];
__device__ float g_lpart[NH * S_LEN * 16];
__device__ float g_E[(size_t)NH * S_LEN * S_LEN];   // exp'd scores (unnormalized)

// ---------------------------------------------------------------------------
__device__ __forceinline__ float tf32r(float x) {
    uint32_t u;
    asm("cvt.rna.tf32.f32 %0, %1;" : "=r"(u) : "f"(x));
    return __uint_as_float(u);
}
__device__ __forceinline__ float ex2f(float x) {
    float y;
    asm("ex2.approx.ftz.f32 %0, %1;" : "=f"(y) : "f"(x));
    return y;
}
__device__ __forceinline__ void mma_tf32(float* c, const uint32_t* a, const uint32_t* b) {
    asm volatile(
        "mma.sync.aligned.m16n8k8.row.col.f32.tf32.tf32.f32 "
        "{%0,%1,%2,%3}, {%4,%5,%6,%7}, {%8,%9}, {%0,%1,%2,%3};"
        : "+f"(c[0]), "+f"(c[1]), "+f"(c[2]), "+f"(c[3])
        : "r"(a[0]), "r"(a[1]), "r"(a[2]), "r"(a[3]), "r"(b[0]), "r"(b[1]));
}
__device__ __forceinline__ void ldsm4(uint32_t& r0, uint32_t& r1, uint32_t& r2, uint32_t& r3,
                                      uint32_t addr) {
    asm volatile("ldmatrix.sync.aligned.m8n8.x4.shared.b16 {%0,%1,%2,%3}, [%4];"
                 : "=r"(r0), "=r"(r1), "=r"(r2), "=r"(r3) : "r"(addr));
}
__device__ __forceinline__ void cpa16(uint32_t s, const float* g) {
    asm volatile("cp.async.cg.shared.global [%0], [%1], 16;" :: "r"(s), "l"(g));
}
__device__ __forceinline__ void cp_commit() { asm volatile("cp.async.commit_group;"); }
template<int N> __device__ __forceinline__ void cp_wait() {
    asm volatile("cp.async.wait_group %0;" :: "n"(N));
}
__device__ __forceinline__ unsigned encf(float x) {
    unsigned b = __float_as_uint(x);
    return (b & 0x80000000u) ? ~b : (b | 0x80000000u);
}

__global__ void zero_kernel(float* p, int n) {
    int i = blockIdx.x * 256 + threadIdx.x;
    if (i < n) p[i] = 0.0f;
}
__global__ void round4_kernel(float4* dst, const float4* src, int n4) {
    int i = blockIdx.x * 256 + threadIdx.x;
    if (i < n4) {
        float4 v = src[i];
        dst[i] = make_float4(tf32r(v.x), tf32r(v.y), tf32r(v.z), tf32r(v.w));
    }
}
// transpose + round: src [Kd][Nd] -> dst [Nd][Kd]
__global__ __launch_bounds__(256) void trr_kernel(float* dst, const float* src, int Kd, int Nd) {
    __shared__ float t[32][33];
    const int bx = blockIdx.x * 32;   // n
    const int by = blockIdx.y * 32;   // k
    const int tx = threadIdx.x, ty = threadIdx.y;
#pragma unroll
    for (int i = 0; i < 32; i += 8)
        t[ty + i][tx] = src[(size_t)(by + ty + i) * Nd + bx + tx];
    __syncthreads();
#pragma unroll
    for (int i = 0; i < 32; i += 8)
        dst[(size_t)(bx + ty + i) * Kd + by + tx] = tf32r(t[tx][ty + i]);
}

// ---------------------------------------------------------------------------
// tf32 GEMM with ldmatrix frags + cp.async double buffer.
// A [M][KD] row-major, Bt [N][KD] row-major (pre-transposed), both tf32-rounded.
// BM=BN=128, BK=16, 256 threads, warps 2m x 4n, WM=64, WN=32.
// blockIdx.z selects (Bt,bias,C).
// ---------------------------------------------------------------------------
template<bool ROUND, bool HASBIAS>
__global__ __launch_bounds__(256) void gemm_lm(
    const float* __restrict__ A,
    const float* __restrict__ Bt0, const float* __restrict__ Bt1,
    const float* __restrict__ bias0, const float* __restrict__ bias1,
    float* __restrict__ C0, float* __restrict__ C1, int N)
{
    constexpr int KD = 2048, BK = 16, ASS = 20;
    constexpr int NIT = KD / BK;

    __shared__ float As[2][128 * ASS];
    __shared__ float Bs[2][128 * ASS];

    const int tid = threadIdx.x;
    const int lane = tid & 31, w = tid >> 5;
    const int wm0 = (w & 1) * 64;
    const int wn0 = (w >> 1) * 32;
    const int bm = blockIdx.y * 128;
    const int bn = blockIdx.x * 128;

    const float* Bt  = (blockIdx.z == 0) ? Bt0 : Bt1;
    const float* bia = (blockIdx.z == 0) ? bias0 : bias1;
    float* C         = (blockIdx.z == 0) ? C0 : C1;

    const int cr = tid & 127;
    const int cc8 = (tid >> 7) * 8;
    const uint32_t sA = (uint32_t)__cvta_generic_to_shared(&As[0][0]);
    const uint32_t sB = (uint32_t)__cvta_generic_to_shared(&Bs[0][0]);

    // ldmatrix lane offsets
    const int g = lane >> 3, r = lane & 7;
    const int a_ro = (g & 1) * 8 + r, a_co = (g >> 1) * 4;
    const int b_ro = (g >> 1) * 8 + r, b_co = (g & 1) * 4;

    float acc[4][4][4];
#pragma unroll
    for (int mi = 0; mi < 4; mi++)
#pragma unroll
        for (int nj = 0; nj < 4; nj++)
#pragma unroll
            for (int c = 0; c < 4; c++) acc[mi][nj][c] = 0.0f;

    auto issue = [&](int st, int k0) {
        const float* ga = &A[(size_t)(bm + cr) * KD + k0 + cc8];
        uint32_t sa = sA + (uint32_t)((st * 128 + cr) * ASS + cc8) * 4u;
        cpa16(sa, ga); cpa16(sa + 16, ga + 4);
        const float* gb = &Bt[(size_t)(bn + cr) * KD + k0 + cc8];
        uint32_t sb = sB + (uint32_t)((st * 128 + cr) * ASS + cc8) * 4u;
        cpa16(sb, gb); cpa16(sb + 16, gb + 4);
    };

    issue(0, 0);
    cp_commit();

    for (int it = 0; it < NIT; it++) {
        if (it + 1 < NIT) {
            issue((it + 1) & 1, (it + 1) * BK);
            cp_commit();
            cp_wait<1>();
        } else {
            cp_wait<0>();
        }
        __syncthreads();
        const uint32_t aB = sA + (uint32_t)((it & 1) * 128 * ASS) * 4u;
        const uint32_t bB = sB + (uint32_t)((it & 1) * 128 * ASS) * 4u;

        uint32_t af[2][4][4], bf[2][4][2];
#pragma unroll
        for (int ks = 0; ks < 2; ks++) {
            const int kk = ks * 8;
#pragma unroll
            for (int mi = 0; mi < 4; mi++) {
                uint32_t ad = aB + (uint32_t)(((wm0 + 16 * mi + a_ro) * ASS) + kk + a_co) * 4u;
                ldsm4(af[ks][mi][0], af[ks][mi][1], af[ks][mi][2], af[ks][mi][3], ad);
            }
#pragma unroll
            for (int p = 0; p < 2; p++) {
                uint32_t bd = bB + (uint32_t)(((wn0 + 16 * p + b_ro) * ASS) + kk + b_co) * 4u;
                ldsm4(bf[ks][2 * p][0], bf[ks][2 * p][1], bf[ks][2 * p + 1][0], bf[ks][2 * p + 1][1], bd);
            }
        }
#pragma unroll
        for (int ks = 0; ks < 2; ks++)
#pragma unroll
            for (int mi = 0; mi < 4; mi++)
#pragma unroll
                for (int nj = 0; nj < 4; nj++)
                    mma_tf32(acc[mi][nj], af[ks][mi], bf[ks][nj]);
        __syncthreads();
    }

#pragma unroll
    for (int mi = 0; mi < 4; mi++) {
#pragma unroll
        for (int nj = 0; nj < 4; nj++) {
            int row = bm + wm0 + 16 * mi + (lane >> 2);
            int col = bn + wn0 + 8 * nj + 2 * (lane & 3);
            float bx = 0.0f, by = 0.0f;
            if (HASBIAS) { bx = bia[col]; by = bia[col + 1]; }
            float v0x = acc[mi][nj][0] + bx, v0y = acc[mi][nj][1] + by;
            float v1x = acc[mi][nj][2] + bx, v1y = acc[mi][nj][3] + by;
            if (ROUND) {
                v0x = tf32r(v0x); v0y = tf32r(v0y);
                v1x = tf32r(v1x); v1y = tf32r(v1y);
            }
            *(float2*)&C[(size_t)row * N + col] = make_float2(v0x, v0y);
            *(float2*)&C[(size_t)(row + 8) * N + col] = make_float2(v1x, v1y);
        }
    }
}

// ---------------------------------------------------------------------------
// Scores kernel: E = 2^(QK^T * scale * log2e) causal-masked, + per-128-block
// row-sum partials into g_lpart. Q [m][2048] (A), K [n][512] (B, [n][k]).
// ---------------------------------------------------------------------------
__global__ __launch_bounds__(256) void scores_lm() {
    constexpr int ASS = 20, BK = 16;
    const int nb = blockIdx.x, mb = blockIdx.y, h = blockIdx.z;
    if (nb > mb) return;
    const int kvh = h >> 2;

    __shared__ float As[2][128 * ASS];
    __shared__ float Bs[2][128 * ASS];
    __shared__ float red[128 * 4];

    const int tid = threadIdx.x;
    const int lane = tid & 31, w = tid >> 5;
    const int wm0 = (w & 1) * 64;
    const int wn0 = (w >> 1) * 32;

    const int cr = tid & 127;
    const int cc8 = (tid >> 7) * 8;
    const uint32_t sA = (uint32_t)__cvta_generic_to_shared(&As[0][0]);
    const uint32_t sB = (uint32_t)__cvta_generic_to_shared(&Bs[0][0]);

    const int g = lane >> 3, r = lane & 7;
    const int a_ro = (g & 1) * 8 + r, a_co = (g >> 1) * 4;
    const int b_ro = (g >> 1) * 8 + r, b_co = (g & 1) * 4;

    const float* Qg = g_q + (size_t)(mb * 128) * DMODEL + h * HDIM;
    const float* Kg = g_k + (size_t)(nb * 128) * KV_DM + kvh * HDIM;

    float acc[4][4][4];
#pragma unroll
    for (int mi = 0; mi < 4; mi++)
#pragma unroll
        for (int nj = 0; nj < 4; nj++)
#pragma unroll
            for (int c = 0; c < 4; c++) acc[mi][nj][c] = 0.0f;

    auto issue = [&](int st, int k0) {
        const float* ga = &Qg[(size_t)cr * DMODEL + k0 + cc8];
        uint32_t sa = sA + (uint32_t)((st * 128 + cr) * ASS + cc8) * 4u;
        cpa16(sa, ga); cpa16(sa + 16, ga + 4);
        const float* gb = &Kg[(size_t)cr * KV_DM + k0 + cc8];
        uint32_t sb = sB + (uint32_t)((st * 128 + cr) * ASS + cc8) * 4u;
        cpa16(sb, gb); cpa16(sb + 16, gb + 4);
    };

    issue(0, 0);
    cp_commit();

    for (int it = 0; it < HDIM / BK; it++) {
        if (it + 1 < HDIM / BK) {
            issue((it + 1) & 1, (it + 1) * BK);
            cp_commit();
            cp_wait<1>();
        } else {
            cp_wait<0>();
        }
        __syncthreads();
        const uint32_t aB = sA + (uint32_t)((it & 1) * 128 * ASS) * 4u;
        const uint32_t bB = sB + (uint32_t)((it & 1) * 128 * ASS) * 4u;
        uint32_t af[2][4][4], bf[2][4][2];
#pragma unroll
        for (int ks = 0; ks < 2; ks++) {
            const int kk = ks * 8;
#pragma unroll
            for (int mi = 0; mi < 4; mi++) {
                uint32_t ad = aB + (uint32_t)(((wm0 + 16 * mi + a_ro) * ASS) + kk + a_co) * 4u;
                ldsm4(af[ks][mi][0], af[ks][mi][1], af[ks][mi][2], af[ks][mi][3], ad);
            }
#pragma unroll
            for (int p = 0; p < 2; p++) {
                uint32_t bd = bB + (uint32_t)(((wn0 + 16 * p + b_ro) * ASS) + kk + b_co) * 4u;
                ldsm4(bf[ks][2 * p][0], bf[ks][2 * p][1], bf[ks][2 * p + 1][0], bf[ks][2 * p + 1][1], bd);
            }
        }
#pragma unroll
        for (int ks = 0; ks < 2; ks++)
#pragma unroll
            for (int mi = 0; mi < 4; mi++)
#pragma unroll
                for (int nj = 0; nj < 4; nj++)
                    mma_tf32(acc[mi][nj], af[ks][mi], bf[ks][nj]);
        __syncthreads();
    }

    const float SCL2 = 0.08838834764831845f * 1.4426950408889634f;
    float* Eh = g_E + (size_t)h * S_LEN * S_LEN;
    float rs[4][2];
#pragma unroll
    for (int mi = 0; mi < 4; mi++) { rs[mi][0] = 0.f; rs[mi][1] = 0.f; }

#pragma unroll
    for (int mi = 0; mi < 4; mi++) {
#pragma unroll
        for (int nj = 0; nj < 4; nj++) {
            int row = mb * 128 + wm0 + 16 * mi + (lane >> 2);
            int col = nb * 128 + wn0 + 8 * nj + 2 * (lane & 3);
            float e0 = (col     <= row)     ? ex2f(acc[mi][nj][0] * SCL2) : 0.f;
            float e1 = (col + 1 <= row)     ? ex2f(acc[mi][nj][1] * SCL2) : 0.f;
            float e2 = (col     <= row + 8) ? ex2f(acc[mi][nj][2] * SCL2) : 0.f;
            float e3 = (col + 1 <= row + 8) ? ex2f(acc[mi][nj][3] * SCL2) : 0.f;
            *(float2*)&Eh[(size_t)row * S_LEN + col] = make_float2(e0, e1);
            *(float2*)&Eh[(size_t)(row + 8) * S_LEN + col] = make_float2(e2, e3);
            rs[mi][0] += e0 + e1;
            rs[mi][1] += e2 + e3;
        }
    }
    // reduce row-sums across lane quads
#pragma unroll
    for (int mi = 0; mi < 4; mi++)
#pragma unroll
        for (int hh = 0; hh < 2; hh++) {
            rs[mi][hh] += __shfl_xor_sync(0xFFFFFFFFu, rs[mi][hh], 1);
            rs[mi][hh] += __shfl_xor_sync(0xFFFFFFFFu, rs[mi][hh], 2);
        }
    if ((lane & 3) == 0) {
        int wg = w >> 1;
#pragma unroll
        for (int mi = 0; mi < 4; mi++) {
            red[(wm0 + 16 * mi + (lane >> 2)) * 4 + wg]     = rs[mi][0];
            red[(wm0 + 16 * mi + 8 + (lane >> 2)) * 4 + wg] = rs[mi][1];
        }
    }
    __syncthreads();
    if (tid < 128)
        g_lpart[((size_t)h * S_LEN + mb * 128 + tid) * 16 + nb] =
            red[tid * 4] + red[tid * 4 + 1] + red[tid * 4 + 2] + red[tid * 4 + 3];
}

// ---------------------------------------------------------------------------
// Attention over E: single pass. p = E * il -> smem, colsums + P@V.
// 512 threads, warps 4m x 4n; 128q block.
// ---------------------------------------------------------------------------
#define SP_OFF   0
#define VS_OFF   8704
#define RED_OFF  17408
#define IL_OFF   17920
#define ATTN_SMEM ((17920 + 128) * 4)

__global__ __launch_bounds__(512, 1) void attn_pv() {
    extern __shared__ float smem[];
    float* sP  = smem + SP_OFF;     // [128][68]
    float* Vs  = smem + VS_OFF;     // [64][136]
    float* red = smem + RED_OFF;    // [512]
    float* il  = smem + IL_OFF;     // [128]

    const int qt = 15 - blockIdx.x;
    const int h  = blockIdx.y;
    const int kvh = h >> 2;
    const int qbase = qt * 128;
    const int tid = threadIdx.x;
    const int lane = tid & 31, w = tid >> 5;
    const int wm  = (w & 3) * 32;
    const int wn2 = (w >> 2) * 32;

    const int g = lane >> 3, r = lane & 7;
    const int a_ro = (g & 1) * 8 + r, a_co = (g >> 1) * 4;
    const uint32_t sPT = (uint32_t)__cvta_generic_to_shared(sP);

    const float* Eh = g_E + (size_t)h * S_LEN * S_LEN;

    if (tid < 128) {
        const float* lp = &g_lpart[((size_t)h * S_LEN + qbase + tid) * 16];
        float l = 0.0f;
        for (int nb = 0; nb <= qt; nb++) l += lp[nb];
        il[tid] = 1.0f / l;
    }
    __syncthreads();

    const int prow = tid >> 2;
    const int pcb = (tid & 3) * 16;
    const float myil = il[prow];

    float o[2][4][4];
#pragma unroll
    for (int mi = 0; mi < 2; mi++)
#pragma unroll
        for (int nj = 0; nj < 4; nj++)
#pragma unroll
            for (int c = 0; c < 4; c++) o[mi][nj][c] = 0.0f;

    const int nkt = 2 * qt + 2;
    for (int kt = 0; kt < nkt; kt++) {
        // load P tile = E * il  and V tile
        {
            const float* ep = &Eh[(size_t)(qbase + prow) * S_LEN + kt * 64 + pcb];
#pragma unroll
            for (int i = 0; i < 4; i++) {
                float4 v = *(const float4*)&ep[4 * i];
                v.x *= myil; v.y *= myil; v.z *= myil; v.w *= myil;
                *(float4*)&sP[prow * 68 + pcb + 4 * i] = v;
            }
            int vr = tid >> 3, vcb = (tid & 7) * 16;
            const float* vp = &g_v[(size_t)(kt * 64 + vr) * KV_DM + kvh * HDIM + vcb];
#pragma unroll
            for (int i = 0; i < 4; i++)
                *(float4*)&Vs[vr * 136 + vcb + 4 * i] = *(const float4*)&vp[4 * i];
        }
        __syncthreads();

        // colsum partials
        if (tid < 256) {
            int c = tid & 63, seg = tid >> 6;
            float cs = 0.0f;
#pragma unroll 8
            for (int q = 0; q < 32; q++) cs += sP[(seg * 32 + q) * 68 + c];
            red[c * 4 + seg] = cs;
        }

        // P@V
#pragma unroll
        for (int ks = 0; ks < 8; ks++) {
            const int kk = ks * 8;
            uint32_t af[2][4], bf[4][2];
#pragma unroll
            for (int mi = 0; mi < 2; mi++) {
                uint32_t ad = sPT + (uint32_t)(((wm + 16 * mi + a_ro) * 68) + kk + a_co) * 4u;
                ldsm4(af[mi][0], af[mi][1], af[mi][2], af[mi][3], ad);
            }
#pragma unroll
            for (int nj = 0; nj < 4; nj++) {
                int n0 = wn2 + 8 * nj + (lane >> 2);
                bf[nj][0] = __float_as_uint(Vs[(kk + (lane & 3)) * 136 + n0]);
                bf[nj][1] = __float_as_uint(Vs[(kk + 4 + (lane & 3)) * 136 + n0]);
            }
#pragma unroll
            for (int mi = 0; mi < 2; mi++)
#pragma unroll
                for (int nj = 0; nj < 4; nj++)
                    mma_tf32(o[mi][nj], af[mi], bf[nj]);
        }
        __syncthreads();
        if (tid < 64)
            g_colpart[((size_t)h * NQT16 + qt) * S_LEN + kt * 64 + tid] =
                red[tid * 4] + red[tid * 4 + 1] + red[tid * 4 + 2] + red[tid * 4 + 3];
    }

#pragma unroll
    for (int mi = 0; mi < 2; mi++)
#pragma unroll
        for (int nj = 0; nj < 4; nj++) {
            int row = qbase + wm + 16 * mi + (lane >> 2);
            int col = h * HDIM + wn2 + 8 * nj + 2 * (lane & 3);
            *(float2*)&g_ctx[(size_t)row * DMODEL + col] =
                make_float2(tf32r(o[mi][nj][0]), tf32r(o[mi][nj][1]));
            *(float2*)&g_ctx[(size_t)(row + 8) * DMODEL + col] =
                make_float2(tf32r(o[mi][nj][2]), tf32r(o[mi][nj][3]));
        }
}

// ---------------------------------------------------------------------------
// Heavy-hitter mask via bitonic sort (exact jax.lax.top_k tie semantics).
// ---------------------------------------------------------------------------
__global__ __launch_bounds__(1024) void topk_kernel(float* __restrict__ mask_out) {
    const int h = blockIdx.x;
    const int tid = threadIdx.x;
    __shared__ unsigned long long keys[2048];

    for (int i = tid; i < 2048; i += 1024) {
        unsigned ev = 0u;
        if (i < SEL) {
            float s = 0.0f;
#pragma unroll
            for (int qt = 0; qt < NQT16; qt++)
                s += g_colpart[((size_t)h * NQT16 + qt) * S_LEN + i];
            ev = encf(s);
        }
        keys[i] = ((unsigned long long)ev << 32) | (unsigned)(2047 - i);
    }
    float* mrow = mask_out + (size_t)h * MASKW;
    for (int i = tid; i < MASKW; i += 1024)
        mrow[i] = (i >= (MASKW - RECENT)) ? 1.0f : 0.0f;
    __syncthreads();

    for (int k = 2; k <= 2048; k <<= 1) {
        for (int j = k >> 1; j > 0; j >>= 1) {
            for (int idx = tid; idx < 2048; idx += 1024) {
                int ixj = idx ^ j;
                if (ixj > idx) {
                    unsigned long long a = keys[idx], b = keys[ixj];
                    bool up = (idx & k) == 0;
                    if (up ? (a > b) : (a < b)) { keys[idx] = b; keys[ixj] = a; }
                }
            }
            __syncthreads();
        }
    }
    for (int i = 2048 - HEAVY + tid; i < 2048; i += 1024) {
        int idx = 2047 - (int)(keys[i] & 0xFFFFFFFFu);
        mrow[idx] = 1.0f;
    }
}

// ---------------------------------------------------------------------------
extern "C" void kernel_launch(void* const* d_in, const int* in_sizes, int n_in,
                              void* d_out, int out_size) {
    (void)in_sizes; (void)n_in; (void)out_size;
    const float* hidden = (const float*)d_in[0];
    const float* q_w = (const float*)d_in[1];
    const float* q_b = (const float*)d_in[2];
    const float* k_w = (const float*)d_in[3];
    const float* k_b = (const float*)d_in[4];
    const float* v_w = (const float*)d_in[5];
    const float* v_b = (const float*)d_in[6];
    const float* o_w = (const float*)d_in[7];
    float* out = (float*)d_out;

    static bool attr_set = false;
    if (!attr_set) {
        cudaFuncSetAttribute(attn_pv, cudaFuncAttributeMaxDynamicSharedMemorySize, ATTN_SMEM);
        attr_set = true;
    }

    float *ghid, *gqwT, *gkwT, *gvwT, *gowT, *gq, *gk, *gv, *gctx, *gcp;
    cudaGetSymbolAddress((void**)&ghid, g_hid);
    cudaGetSymbolAddress((void**)&gqwT, g_qwT);
    cudaGetSymbolAddress((void**)&gkwT, g_kwT);
    cudaGetSymbolAddress((void**)&gvwT, g_vwT);
    cudaGetSymbolAddress((void**)&gowT, g_owT);
    cudaGetSymbolAddress((void**)&gq,   g_q);
    cudaGetSymbolAddress((void**)&gk,   g_k);
    cudaGetSymbolAddress((void**)&gv,   g_v);
    cudaGetSymbolAddress((void**)&gctx, g_ctx);
    cudaGetSymbolAddress((void**)&gcp,  g_colpart);

    round4_kernel<<<(S_LEN * DMODEL / 4 + 255) / 256, 256>>>(
        (float4*)ghid, (const float4*)hidden, S_LEN * DMODEL / 4);
    dim3 tb(32, 8);
    trr_kernel<<<dim3(DMODEL / 32, DMODEL / 32), tb>>>(gqwT, q_w, DMODEL, DMODEL);
    trr_kernel<<<dim3(KV_DM / 32, DMODEL / 32), tb>>>(gkwT, k_w, DMODEL, KV_DM);
    trr_kernel<<<dim3(KV_DM / 32, DMODEL / 32), tb>>>(gvwT, v_w, DMODEL, KV_DM);
    trr_kernel<<<dim3(DMODEL / 32, DMODEL / 32), tb>>>(gowT, o_w, DMODEL, DMODEL);

    const int ncp = NH * NQT16 * S_LEN;
    zero_kernel<<<(ncp + 255) / 256, 256>>>(gcp, ncp);

    gemm_lm<true, true><<<dim3(DMODEL / 128, S_LEN / 128, 1), 256>>>(
        ghid, gqwT, nullptr, q_b, nullptr, gq, nullptr, DMODEL);
    gemm_lm<true, true><<<dim3(KV_DM / 128, S_LEN / 128, 2), 256>>>(
        ghid, gkwT, gvwT, k_b, v_b, gk, gv, KV_DM);

    scores_lm<<<dim3(16, 16, NH), 256>>>();

    attn_pv<<<dim3(16, NH), 512, ATTN_SMEM>>>();

    topk_kernel<<<NH, 1024>>>(out + (size_t)S_LEN * DMODEL);

    gemm_lm<false, false><<<dim3(DMODEL / 128, S_LEN / 128, 1), 256>>>(
        gctx, gowT, nullptr, nullptr, nullptr, out, nullptr, DMODEL);
}

// round 6
// speedup vs baseline: 1.1858x; 1.0473x over previous
#include <cuda_runtime.h>
#include <cstdint>

#define S_LEN   2048
#define DMODEL  2048
#define NH      16
#define HDIM    128
#define KV_DM   512
#define NQT16   16
#define HEAVY   204
#define RECENT  204
#define SEL     (S_LEN - RECENT)    // 1844
#define MASKW   (S_LEN + 1)         // 2049

__device__ float g_hid[S_LEN * DMODEL];
__device__ float g_qwT[DMODEL * DMODEL];   // [n][k]
__device__ float g_kwT[KV_DM * DMODEL];
__device__ float g_vwT[KV_DM * DMODEL];
__device__ float g_owT[DMODEL * DMODEL];
__device__ float g_q[S_LEN * DMODEL];
__device__ float g_k[S_LEN * KV_DM];
__device__ float g_v[S_LEN * KV_DM];
__device__ float g_ctx[S_LEN * DMODEL];
__device__ float g_colpart[NH * NQT16 * S_LEN];
__device__ float g_lpart[NH * S_LEN * 16];
__device__ float g_E[(size_t)NH * S_LEN * S_LEN];   // exp'd scores (unnormalized)

// ---------------------------------------------------------------------------
__device__ __forceinline__ float tf32r(float x) {
    uint32_t u;
    asm("cvt.rna.tf32.f32 %0, %1;" : "=r"(u) : "f"(x));
    return __uint_as_float(u);
}
__device__ __forceinline__ float ex2f(float x) {
    float y;
    asm("ex2.approx.ftz.f32 %0, %1;" : "=f"(y) : "f"(x));
    return y;
}
__device__ __forceinline__ void mma_tf32(float* c, const uint32_t* a, const uint32_t* b) {
    asm volatile(
        "mma.sync.aligned.m16n8k8.row.col.f32.tf32.tf32.f32 "
        "{%0,%1,%2,%3}, {%4,%5,%6,%7}, {%8,%9}, {%0,%1,%2,%3};"
        : "+f"(c[0]), "+f"(c[1]), "+f"(c[2]), "+f"(c[3])
        : "r"(a[0]), "r"(a[1]), "r"(a[2]), "r"(a[3]), "r"(b[0]), "r"(b[1]));
}
__device__ __forceinline__ void ldsm4(uint32_t& r0, uint32_t& r1, uint32_t& r2, uint32_t& r3,
                                      uint32_t addr) {
    asm volatile("ldmatrix.sync.aligned.m8n8.x4.shared.b16 {%0,%1,%2,%3}, [%4];"
                 : "=r"(r0), "=r"(r1), "=r"(r2), "=r"(r3) : "r"(addr));
}
__device__ __forceinline__ void cpa16(uint32_t s, const float* g) {
    asm volatile("cp.async.cg.shared.global [%0], [%1], 16;" :: "r"(s), "l"(g));
}
__device__ __forceinline__ void cp_commit() { asm volatile("cp.async.commit_group;"); }
template<int N> __device__ __forceinline__ void cp_wait() {
    asm volatile("cp.async.wait_group %0;" :: "n"(N));
}
__device__ __forceinline__ unsigned encf(float x) {
    unsigned b = __float_as_uint(x);
    return (b & 0x80000000u) ? ~b : (b | 0x80000000u);
}

__global__ void zero_kernel(float* p, int n) {
    int i = blockIdx.x * 256 + threadIdx.x;
    if (i < n) p[i] = 0.0f;
}
__global__ void round4_kernel(float4* dst, const float4* src, int n4) {
    int i = blockIdx.x * 256 + threadIdx.x;
    if (i < n4) {
        float4 v = src[i];
        dst[i] = make_float4(tf32r(v.x), tf32r(v.y), tf32r(v.z), tf32r(v.w));
    }
}
// transpose + round: src [Kd][Nd] -> dst [Nd][Kd]
__global__ __launch_bounds__(256) void trr_kernel(float* dst, const float* src, int Kd, int Nd) {
    __shared__ float t[32][33];
    const int bx = blockIdx.x * 32;   // n
    const int by = blockIdx.y * 32;   // k
    const int tx = threadIdx.x, ty = threadIdx.y;
#pragma unroll
    for (int i = 0; i < 32; i += 8)
        t[ty + i][tx] = src[(size_t)(by + ty + i) * Nd + bx + tx];
    __syncthreads();
#pragma unroll
    for (int i = 0; i < 32; i += 8)
        dst[(size_t)(bx + ty + i) * Kd + by + tx] = tf32r(t[tx][ty + i]);
}

// ---------------------------------------------------------------------------
// tf32 GEMM with ldmatrix frags + cp.async double buffer.
// A [M][KD] row-major, Bt [N][KD] row-major (pre-transposed), both tf32-rounded.
// BM=BN=128, BK=16, 256 threads, warps 2m x 4n, WM=64, WN=32.
// ---------------------------------------------------------------------------
template<bool ROUND, bool HASBIAS>
__global__ __launch_bounds__(256) void gemm_lm(
    const float* __restrict__ A,
    const float* __restrict__ Bt0, const float* __restrict__ Bt1,
    const float* __restrict__ bias0, const float* __restrict__ bias1,
    float* __restrict__ C0, float* __restrict__ C1, int N)
{
    constexpr int KD = 2048, BK = 16, ASS = 20;
    constexpr int NIT = KD / BK;

    __shared__ float As[2][128 * ASS];
    __shared__ float Bs[2][128 * ASS];

    const int tid = threadIdx.x;
    const int lane = tid & 31, w = tid >> 5;
    const int wm0 = (w & 1) * 64;
    const int wn0 = (w >> 1) * 32;
    const int bm = blockIdx.y * 128;
    const int bn = blockIdx.x * 128;

    const float* Bt  = (blockIdx.z == 0) ? Bt0 : Bt1;
    const float* bia = (blockIdx.z == 0) ? bias0 : bias1;
    float* C         = (blockIdx.z == 0) ? C0 : C1;

    const int cr = tid & 127;
    const int cc8 = (tid >> 7) * 8;
    const uint32_t sA = (uint32_t)__cvta_generic_to_shared(&As[0][0]);
    const uint32_t sB = (uint32_t)__cvta_generic_to_shared(&Bs[0][0]);

    const int g = lane >> 3, r = lane & 7;
    const int a_ro = (g & 1) * 8 + r, a_co = (g >> 1) * 4;
    const int b_ro = (g >> 1) * 8 + r, b_co = (g & 1) * 4;

    float acc[4][4][4];
#pragma unroll
    for (int mi = 0; mi < 4; mi++)
#pragma unroll
        for (int nj = 0; nj < 4; nj++)
#pragma unroll
            for (int c = 0; c < 4; c++) acc[mi][nj][c] = 0.0f;

    auto issue = [&](int st, int k0) {
        const float* ga = &A[(size_t)(bm + cr) * KD + k0 + cc8];
        uint32_t sa = sA + (uint32_t)((st * 128 + cr) * ASS + cc8) * 4u;
        cpa16(sa, ga); cpa16(sa + 16, ga + 4);
        const float* gb = &Bt[(size_t)(bn + cr) * KD + k0 + cc8];
        uint32_t sb = sB + (uint32_t)((st * 128 + cr) * ASS + cc8) * 4u;
        cpa16(sb, gb); cpa16(sb + 16, gb + 4);
    };

    issue(0, 0);
    cp_commit();

    for (int it = 0; it < NIT; it++) {
        if (it + 1 < NIT) {
            issue((it + 1) & 1, (it + 1) * BK);
            cp_commit();
            cp_wait<1>();
        } else {
            cp_wait<0>();
        }
        __syncthreads();
        const uint32_t aB = sA + (uint32_t)((it & 1) * 128 * ASS) * 4u;
        const uint32_t bB = sB + (uint32_t)((it & 1) * 128 * ASS) * 4u;

        uint32_t af[2][4][4], bf[2][4][2];
#pragma unroll
        for (int ks = 0; ks < 2; ks++) {
            const int kk = ks * 8;
#pragma unroll
            for (int mi = 0; mi < 4; mi++) {
                uint32_t ad = aB + (uint32_t)(((wm0 + 16 * mi + a_ro) * ASS) + kk + a_co) * 4u;
                ldsm4(af[ks][mi][0], af[ks][mi][1], af[ks][mi][2], af[ks][mi][3], ad);
            }
#pragma unroll
            for (int p = 0; p < 2; p++) {
                uint32_t bd = bB + (uint32_t)(((wn0 + 16 * p + b_ro) * ASS) + kk + b_co) * 4u;
                ldsm4(bf[ks][2 * p][0], bf[ks][2 * p][1], bf[ks][2 * p + 1][0], bf[ks][2 * p + 1][1], bd);
            }
        }
#pragma unroll
        for (int ks = 0; ks < 2; ks++)
#pragma unroll
            for (int mi = 0; mi < 4; mi++)
#pragma unroll
                for (int nj = 0; nj < 4; nj++)
                    mma_tf32(acc[mi][nj], af[ks][mi], bf[ks][nj]);
        __syncthreads();
    }

#pragma unroll
    for (int mi = 0; mi < 4; mi++) {
#pragma unroll
        for (int nj = 0; nj < 4; nj++) {
            int row = bm + wm0 + 16 * mi + (lane >> 2);
            int col = bn + wn0 + 8 * nj + 2 * (lane & 3);
            float bx = 0.0f, by = 0.0f;
            if (HASBIAS) { bx = bia[col]; by = bia[col + 1]; }
            float v0x = acc[mi][nj][0] + bx, v0y = acc[mi][nj][1] + by;
            float v1x = acc[mi][nj][2] + bx, v1y = acc[mi][nj][3] + by;
            if (ROUND) {
                v0x = tf32r(v0x); v0y = tf32r(v0y);
                v1x = tf32r(v1x); v1y = tf32r(v1y);
            }
            *(float2*)&C[(size_t)row * N + col] = make_float2(v0x, v0y);
            *(float2*)&C[(size_t)(row + 8) * N + col] = make_float2(v1x, v1y);
        }
    }
}

// ---------------------------------------------------------------------------
// Scores kernel: E = 2^(QK^T * scale * log2e) causal-masked, + per-128-block
// row-sum partials into g_lpart.
// ---------------------------------------------------------------------------
__global__ __launch_bounds__(256) void scores_lm() {
    constexpr int ASS = 20, BK = 16;
    const int nb = blockIdx.x, mb = blockIdx.y, h = blockIdx.z;
    if (nb > mb) return;
    const int kvh = h >> 2;

    __shared__ float As[2][128 * ASS];
    __shared__ float Bs[2][128 * ASS];
    __shared__ float red[128 * 4];

    const int tid = threadIdx.x;
    const int lane = tid & 31, w = tid >> 5;
    const int wm0 = (w & 1) * 64;
    const int wn0 = (w >> 1) * 32;

    const int cr = tid & 127;
    const int cc8 = (tid >> 7) * 8;
    const uint32_t sA = (uint32_t)__cvta_generic_to_shared(&As[0][0]);
    const uint32_t sB = (uint32_t)__cvta_generic_to_shared(&Bs[0][0]);

    const int g = lane >> 3, r = lane & 7;
    const int a_ro = (g & 1) * 8 + r, a_co = (g >> 1) * 4;
    const int b_ro = (g >> 1) * 8 + r, b_co = (g & 1) * 4;

    const float* Qg = g_q + (size_t)(mb * 128) * DMODEL + h * HDIM;
    const float* Kg = g_k + (size_t)(nb * 128) * KV_DM + kvh * HDIM;

    float acc[4][4][4];
#pragma unroll
    for (int mi = 0; mi < 4; mi++)
#pragma unroll
        for (int nj = 0; nj < 4; nj++)
#pragma unroll
            for (int c = 0; c < 4; c++) acc[mi][nj][c] = 0.0f;

    auto issue = [&](int st, int k0) {
        const float* ga = &Qg[(size_t)cr * DMODEL + k0 + cc8];
        uint32_t sa = sA + (uint32_t)((st * 128 + cr) * ASS + cc8) * 4u;
        cpa16(sa, ga); cpa16(sa + 16, ga + 4);
        const float* gb = &Kg[(size_t)cr * KV_DM + k0 + cc8];
        uint32_t sb = sB + (uint32_t)((st * 128 + cr) * ASS + cc8) * 4u;
        cpa16(sb, gb); cpa16(sb + 16, gb + 4);
    };

    issue(0, 0);
    cp_commit();

    for (int it = 0; it < HDIM / BK; it++) {
        if (it + 1 < HDIM / BK) {
            issue((it + 1) & 1, (it + 1) * BK);
            cp_commit();
            cp_wait<1>();
        } else {
            cp_wait<0>();
        }
        __syncthreads();
        const uint32_t aB = sA + (uint32_t)((it & 1) * 128 * ASS) * 4u;
        const uint32_t bB = sB + (uint32_t)((it & 1) * 128 * ASS) * 4u;
        uint32_t af[2][4][4], bf[2][4][2];
#pragma unroll
        for (int ks = 0; ks < 2; ks++) {
            const int kk = ks * 8;
#pragma unroll
            for (int mi = 0; mi < 4; mi++) {
                uint32_t ad = aB + (uint32_t)(((wm0 + 16 * mi + a_ro) * ASS) + kk + a_co) * 4u;
                ldsm4(af[ks][mi][0], af[ks][mi][1], af[ks][mi][2], af[ks][mi][3], ad);
            }
#pragma unroll
            for (int p = 0; p < 2; p++) {
                uint32_t bd = bB + (uint32_t)(((wn0 + 16 * p + b_ro) * ASS) + kk + b_co) * 4u;
                ldsm4(bf[ks][2 * p][0], bf[ks][2 * p][1], bf[ks][2 * p + 1][0], bf[ks][2 * p + 1][1], bd);
            }
        }
#pragma unroll
        for (int ks = 0; ks < 2; ks++)
#pragma unroll
            for (int mi = 0; mi < 4; mi++)
#pragma unroll
                for (int nj = 0; nj < 4; nj++)
                    mma_tf32(acc[mi][nj], af[ks][mi], bf[ks][nj]);
        __syncthreads();
    }

    const float SCL2 = 0.08838834764831845f * 1.4426950408889634f;
    float* Eh = g_E + (size_t)h * S_LEN * S_LEN;
    float rs[4][2];
#pragma unroll
    for (int mi = 0; mi < 4; mi++) { rs[mi][0] = 0.f; rs[mi][1] = 0.f; }

#pragma unroll
    for (int mi = 0; mi < 4; mi++) {
#pragma unroll
        for (int nj = 0; nj < 4; nj++) {
            int row = mb * 128 + wm0 + 16 * mi + (lane >> 2);
            int col = nb * 128 + wn0 + 8 * nj + 2 * (lane & 3);
            float e0 = (col     <= row)     ? ex2f(acc[mi][nj][0] * SCL2) : 0.f;
            float e1 = (col + 1 <= row)     ? ex2f(acc[mi][nj][1] * SCL2) : 0.f;
            float e2 = (col     <= row + 8) ? ex2f(acc[mi][nj][2] * SCL2) : 0.f;
            float e3 = (col + 1 <= row + 8) ? ex2f(acc[mi][nj][3] * SCL2) : 0.f;
            *(float2*)&Eh[(size_t)row * S_LEN + col] = make_float2(e0, e1);
            *(float2*)&Eh[(size_t)(row + 8) * S_LEN + col] = make_float2(e2, e3);
            rs[mi][0] += e0 + e1;
            rs[mi][1] += e2 + e3;
        }
    }
#pragma unroll
    for (int mi = 0; mi < 4; mi++)
#pragma unroll
        for (int hh = 0; hh < 2; hh++) {
            rs[mi][hh] += __shfl_xor_sync(0xFFFFFFFFu, rs[mi][hh], 1);
            rs[mi][hh] += __shfl_xor_sync(0xFFFFFFFFu, rs[mi][hh], 2);
        }
    if ((lane & 3) == 0) {
        int wg = w >> 1;
#pragma unroll
        for (int mi = 0; mi < 4; mi++) {
            red[(wm0 + 16 * mi + (lane >> 2)) * 4 + wg]     = rs[mi][0];
            red[(wm0 + 16 * mi + 8 + (lane >> 2)) * 4 + wg] = rs[mi][1];
        }
    }
    __syncthreads();
    if (tid < 128)
        g_lpart[((size_t)h * S_LEN + mb * 128 + tid) * 16 + nb] =
            red[tid * 4] + red[tid * 4 + 1] + red[tid * 4 + 2] + red[tid * 4 + 3];
}

// ---------------------------------------------------------------------------
// Attention over E: single pass. p = E * il -> smem, colsums + P@V.
// ---------------------------------------------------------------------------
#define SP_OFF   0
#define VS_OFF   8704
#define RED_OFF  17408
#define IL_OFF   17920
#define ATTN_SMEM ((17920 + 128) * 4)

__global__ __launch_bounds__(512, 1) void attn_pv() {
    extern __shared__ float smem[];
    float* sP  = smem + SP_OFF;     // [128][68]
    float* Vs  = smem + VS_OFF;     // [64][136]
    float* red = smem + RED_OFF;    // [512]
    float* il  = smem + IL_OFF;     // [128]

    const int qt = 15 - blockIdx.x;
    const int h  = blockIdx.y;
    const int kvh = h >> 2;
    const int qbase = qt * 128;
    const int tid = threadIdx.x;
    const int lane = tid & 31, w = tid >> 5;
    const int wm  = (w & 3) * 32;
    const int wn2 = (w >> 2) * 32;

    const int g = lane >> 3, r = lane & 7;
    const int a_ro = (g & 1) * 8 + r, a_co = (g >> 1) * 4;
    const uint32_t sPT = (uint32_t)__cvta_generic_to_shared(sP);

    const float* Eh = g_E + (size_t)h * S_LEN * S_LEN;

    if (tid < 128) {
        const float* lp = &g_lpart[((size_t)h * S_LEN + qbase + tid) * 16];
        float l = 0.0f;
        for (int nb = 0; nb <= qt; nb++) l += lp[nb];
        il[tid] = 1.0f / l;
    }
    __syncthreads();

    const int prow = tid >> 2;
    const int pcb = (tid & 3) * 16;
    const float myil = il[prow];

    float o[2][4][4];
#pragma unroll
    for (int mi = 0; mi < 2; mi++)
#pragma unroll
        for (int nj = 0; nj < 4; nj++)
#pragma unroll
            for (int c = 0; c < 4; c++) o[mi][nj][c] = 0.0f;

    const int nkt = 2 * qt + 2;
    for (int kt = 0; kt < nkt; kt++) {
        {
            const float* ep = &Eh[(size_t)(qbase + prow) * S_LEN + kt * 64 + pcb];
#pragma unroll
            for (int i = 0; i < 4; i++) {
                float4 v = *(const float4*)&ep[4 * i];
                v.x *= myil; v.y *= myil; v.z *= myil; v.w *= myil;
                *(float4*)&sP[prow * 68 + pcb + 4 * i] = v;
            }
            int vr = tid >> 3, vcb = (tid & 7) * 16;
            const float* vp = &g_v[(size_t)(kt * 64 + vr) * KV_DM + kvh * HDIM + vcb];
#pragma unroll
            for (int i = 0; i < 4; i++)
                *(float4*)&Vs[vr * 136 + vcb + 4 * i] = *(const float4*)&vp[4 * i];
        }
        __syncthreads();

        if (tid < 256) {
            int c = tid & 63, seg = tid >> 6;
            float cs = 0.0f;
#pragma unroll 8
            for (int q = 0; q < 32; q++) cs += sP[(seg * 32 + q) * 68 + c];
            red[c * 4 + seg] = cs;
        }

#pragma unroll
        for (int ks = 0; ks < 8; ks++) {
            const int kk = ks * 8;
            uint32_t af[2][4], bf[4][2];
#pragma unroll
            for (int mi = 0; mi < 2; mi++) {
                uint32_t ad = sPT + (uint32_t)(((wm + 16 * mi + a_ro) * 68) + kk + a_co) * 4u;
                ldsm4(af[mi][0], af[mi][1], af[mi][2], af[mi][3], ad);
            }
#pragma unroll
            for (int nj = 0; nj < 4; nj++) {
                int n0 = wn2 + 8 * nj + (lane >> 2);
                bf[nj][0] = __float_as_uint(Vs[(kk + (lane & 3)) * 136 + n0]);
                bf[nj][1] = __float_as_uint(Vs[(kk + 4 + (lane & 3)) * 136 + n0]);
            }
#pragma unroll
            for (int mi = 0; mi < 2; mi++)
#pragma unroll
                for (int nj = 0; nj < 4; nj++)
                    mma_tf32(o[mi][nj], af[mi], bf[nj]);
        }
        __syncthreads();
        if (tid < 64)
            g_colpart[((size_t)h * NQT16 + qt) * S_LEN + kt * 64 + tid] =
                red[tid * 4] + red[tid * 4 + 1] + red[tid * 4 + 2] + red[tid * 4 + 3];
    }

#pragma unroll
    for (int mi = 0; mi < 2; mi++)
#pragma unroll
        for (int nj = 0; nj < 4; nj++) {
            int row = qbase + wm + 16 * mi + (lane >> 2);
            int col = h * HDIM + wn2 + 8 * nj + 2 * (lane & 3);
            *(float2*)&g_ctx[(size_t)row * DMODEL + col] =
                make_float2(tf32r(o[mi][nj][0]), tf32r(o[mi][nj][1]));
            *(float2*)&g_ctx[(size_t)(row + 8) * DMODEL + col] =
                make_float2(tf32r(o[mi][nj][2]), tf32r(o[mi][nj][3]));
        }
}

// ---------------------------------------------------------------------------
// Heavy-hitter mask via bitonic sort (exact jax.lax.top_k tie semantics).
// ---------------------------------------------------------------------------
__global__ __launch_bounds__(1024) void topk_kernel(float* __restrict__ mask_out) {
    const int h = blockIdx.x;
    const int tid = threadIdx.x;
    __shared__ unsigned long long keys[2048];

    for (int i = tid; i < 2048; i += 1024) {
        unsigned ev = 0u;
        if (i < SEL) {
            float s = 0.0f;
#pragma unroll
            for (int qt = 0; qt < NQT16; qt++)
                s += g_colpart[((size_t)h * NQT16 + qt) * S_LEN + i];
            ev = encf(s);
        }
        keys[i] = ((unsigned long long)ev << 32) | (unsigned)(2047 - i);
    }
    float* mrow = mask_out + (size_t)h * MASKW;
    for (int i = tid; i < MASKW; i += 1024)
        mrow[i] = (i >= (MASKW - RECENT)) ? 1.0f : 0.0f;
    __syncthreads();

    for (int k = 2; k <= 2048; k <<= 1) {
        for (int j = k >> 1; j > 0; j >>= 1) {
            for (int idx = tid; idx < 2048; idx += 1024) {
                int ixj = idx ^ j;
                if (ixj > idx) {
                    unsigned long long a = keys[idx], b = keys[ixj];
                    bool up = (idx & k) == 0;
                    if (up ? (a > b) : (a < b)) { keys[idx] = b; keys[ixj] = a; }
                }
            }
            __syncthreads();
        }
    }
    for (int i = 2048 - HEAVY + tid; i < 2048; i += 1024) {
        int idx = 2047 - (int)(keys[i] & 0xFFFFFFFFu);
        mrow[idx] = 1.0f;
    }
}

// ---------------------------------------------------------------------------
extern "C" void kernel_launch(void* const* d_in, const int* in_sizes, int n_in,
                              void* d_out, int out_size) {
    (void)in_sizes; (void)n_in; (void)out_size;
    const float* hidden = (const float*)d_in[0];
    const float* q_w = (const float*)d_in[1];
    const float* q_b = (const float*)d_in[2];
    const float* k_w = (const float*)d_in[3];
    const float* k_b = (const float*)d_in[4];
    const float* v_w = (const float*)d_in[5];
    const float* v_b = (const float*)d_in[6];
    const float* o_w = (const float*)d_in[7];
    float* out = (float*)d_out;

    static bool init = false;
    static cudaStream_t sA, sB, sC;
    static cudaEvent_t evRoot, evHid, evKV, evZero, evAttn, evTrrO, evDoneA, evDoneC;
    if (!init) {
        cudaFuncSetAttribute(attn_pv, cudaFuncAttributeMaxDynamicSharedMemorySize, ATTN_SMEM);
        cudaStreamCreateWithFlags(&sA, cudaStreamNonBlocking);
        cudaStreamCreateWithFlags(&sB, cudaStreamNonBlocking);
        cudaStreamCreateWithFlags(&sC, cudaStreamNonBlocking);
        cudaEventCreateWithFlags(&evRoot, cudaEventDisableTiming);
        cudaEventCreateWithFlags(&evHid,  cudaEventDisableTiming);
        cudaEventCreateWithFlags(&evKV,   cudaEventDisableTiming);
        cudaEventCreateWithFlags(&evZero, cudaEventDisableTiming);
        cudaEventCreateWithFlags(&evAttn, cudaEventDisableTiming);
        cudaEventCreateWithFlags(&evTrrO, cudaEventDisableTiming);
        cudaEventCreateWithFlags(&evDoneA, cudaEventDisableTiming);
        cudaEventCreateWithFlags(&evDoneC, cudaEventDisableTiming);
        init = true;
    }

    float *ghid, *gqwT, *gkwT, *gvwT, *gowT, *gq, *gk, *gv, *gctx, *gcp;
    cudaGetSymbolAddress((void**)&ghid, g_hid);
    cudaGetSymbolAddress((void**)&gqwT, g_qwT);
    cudaGetSymbolAddress((void**)&gkwT, g_kwT);
    cudaGetSymbolAddress((void**)&gvwT, g_vwT);
    cudaGetSymbolAddress((void**)&gowT, g_owT);
    cudaGetSymbolAddress((void**)&gq,   g_q);
    cudaGetSymbolAddress((void**)&gk,   g_k);
    cudaGetSymbolAddress((void**)&gv,   g_v);
    cudaGetSymbolAddress((void**)&gctx, g_ctx);
    cudaGetSymbolAddress((void**)&gcp,  g_colpart);

    // fork from the capture (legacy) stream
    cudaEventRecord(evRoot, 0);
    cudaStreamWaitEvent(sA, evRoot, 0);
    cudaStreamWaitEvent(sB, evRoot, 0);
    cudaStreamWaitEvent(sC, evRoot, 0);

    dim3 tb(32, 8);
    // sA: round_hid -> trr_q -> gemmQ -> scores -> attn -> gemmO
    round4_kernel<<<(S_LEN * DMODEL / 4 + 255) / 256, 256, 0, sA>>>(
        (float4*)ghid, (const float4*)hidden, S_LEN * DMODEL / 4);
    cudaEventRecord(evHid, sA);
    trr_kernel<<<dim3(DMODEL / 32, DMODEL / 32), tb, 0, sA>>>(gqwT, q_w, DMODEL, DMODEL);
    // sB: trr_k -> trr_v -> (wait hid) -> gemmKV
    trr_kernel<<<dim3(KV_DM / 32, DMODEL / 32), tb, 0, sB>>>(gkwT, k_w, DMODEL, KV_DM);
    trr_kernel<<<dim3(KV_DM / 32, DMODEL / 32), tb, 0, sB>>>(gvwT, v_w, DMODEL, KV_DM);
    // sC: trr_o, zero
    trr_kernel<<<dim3(DMODEL / 32, DMODEL / 32), tb, 0, sC>>>(gowT, o_w, DMODEL, DMODEL);
    cudaEventRecord(evTrrO, sC);

    // 6th kernel submission: Q GEMM (ncu -s 5 -c 1 profiles this)
    gemm_lm<true, true><<<dim3(DMODEL / 128, S_LEN / 128, 1), 256, 0, sA>>>(
        ghid, gqwT, nullptr, q_b, nullptr, gq, nullptr, DMODEL);

    cudaStreamWaitEvent(sB, evHid, 0);
    gemm_lm<true, true><<<dim3(KV_DM / 128, S_LEN / 128, 2), 256, 0, sB>>>(
        ghid, gkwT, gvwT, k_b, v_b, gk, gv, KV_DM);
    cudaEventRecord(evKV, sB);

    const int ncp = NH * NQT16 * S_LEN;
    zero_kernel<<<(ncp + 255) / 256, 256, 0, sC>>>(gcp, ncp);
    cudaEventRecord(evZero, sC);

    cudaStreamWaitEvent(sA, evKV, 0);
    scores_lm<<<dim3(16, 16, NH), 256, 0, sA>>>();

    cudaStreamWaitEvent(sA, evZero, 0);
    attn_pv<<<dim3(16, NH), 512, ATTN_SMEM, sA>>>();
    cudaEventRecord(evAttn, sA);

    // sC: topk (after attn), overlaps with gemmO on sA
    cudaStreamWaitEvent(sC, evAttn, 0);
    topk_kernel<<<NH, 1024, 0, sC>>>(out + (size_t)S_LEN * DMODEL);
    cudaEventRecord(evDoneC, sC);

    cudaStreamWaitEvent(sA, evTrrO, 0);
    gemm_lm<false, false><<<dim3(DMODEL / 128, S_LEN / 128, 1), 256, 0, sA>>>(
        gctx, gowT, nullptr, nullptr, nullptr, out, nullptr, DMODEL);
    cudaEventRecord(evDoneA, sA);

    // join back to the capture stream
    cudaStreamWaitEvent(0, evDoneA, 0);
    cudaStreamWaitEvent(0, evDoneC, 0);
}

// round 7
// speedup vs baseline: 1.2741x; 1.0745x over previous
#include <cuda_runtime.h>
#include <cstdint>

#define S_LEN   2048
#define DMODEL  2048
#define NH      16
#define HDIM    128
#define KV_DM   512
#define NQT16   16
#define HEAVY   204
#define RECENT  204
#define SEL     (S_LEN - RECENT)    // 1844
#define MASKW   (S_LEN + 1)         // 2049

__device__ float g_hid[S_LEN * DMODEL];
__device__ float g_qwT[DMODEL * DMODEL];   // [n][k]
__device__ float g_kwT[KV_DM * DMODEL];
__device__ float g_vwT[KV_DM * DMODEL];
__device__ float g_owT[DMODEL * DMODEL];
__device__ float g_q[S_LEN * DMODEL];
__device__ float g_k[S_LEN * KV_DM];
__device__ float g_v[S_LEN * KV_DM];
__device__ float g_ctx[S_LEN * DMODEL];
__device__ float g_colpart[NH * NQT16 * S_LEN];
__device__ float g_lpart[NH * S_LEN * 16];
__device__ float g_E[(size_t)NH * S_LEN * S_LEN];   // exp'd scores (unnormalized)

// ---------------------------------------------------------------------------
__device__ __forceinline__ float tf32r(float x) {
    uint32_t u;
    asm("cvt.rna.tf32.f32 %0, %1;" : "=r"(u) : "f"(x));
    return __uint_as_float(u);
}
__device__ __forceinline__ float ex2f(float x) {
    float y;
    asm("ex2.approx.ftz.f32 %0, %1;" : "=f"(y) : "f"(x));
    return y;
}
__device__ __forceinline__ void mma_tf32(float* c, const uint32_t* a, const uint32_t* b) {
    asm volatile(
        "mma.sync.aligned.m16n8k8.row.col.f32.tf32.tf32.f32 "
        "{%0,%1,%2,%3}, {%4,%5,%6,%7}, {%8,%9}, {%0,%1,%2,%3};"
        : "+f"(c[0]), "+f"(c[1]), "+f"(c[2]), "+f"(c[3])
        : "r"(a[0]), "r"(a[1]), "r"(a[2]), "r"(a[3]), "r"(b[0]), "r"(b[1]));
}
__device__ __forceinline__ void ldsm4(uint32_t& r0, uint32_t& r1, uint32_t& r2, uint32_t& r3,
                                      uint32_t addr) {
    asm volatile("ldmatrix.sync.aligned.m8n8.x4.shared.b16 {%0,%1,%2,%3}, [%4];"
                 : "=r"(r0), "=r"(r1), "=r"(r2), "=r"(r3) : "r"(addr));
}
__device__ __forceinline__ void cpa16(uint32_t s, const float* g) {
    asm volatile("cp.async.cg.shared.global [%0], [%1], 16;" :: "r"(s), "l"(g));
}
__device__ __forceinline__ void cp_commit() { asm volatile("cp.async.commit_group;"); }
template<int N> __device__ __forceinline__ void cp_wait() {
    asm volatile("cp.async.wait_group %0;" :: "n"(N));
}
__device__ __forceinline__ unsigned encf(float x) {
    unsigned b = __float_as_uint(x);
    return (b & 0x80000000u) ? ~b : (b | 0x80000000u);
}

__global__ void zero_kernel(float* p, int n) {
    int i = blockIdx.x * 256 + threadIdx.x;
    if (i < n) p[i] = 0.0f;
}
__global__ void round4_kernel(float4* dst, const float4* src, int n4) {
    int i = blockIdx.x * 256 + threadIdx.x;
    if (i < n4) {
        float4 v = src[i];
        dst[i] = make_float4(tf32r(v.x), tf32r(v.y), tf32r(v.z), tf32r(v.w));
    }
}
// transpose + round: src [Kd][Nd] -> dst [Nd][Kd]
__global__ __launch_bounds__(256) void trr_kernel(float* dst, const float* src, int Kd, int Nd) {
    __shared__ float t[32][33];
    const int bx = blockIdx.x * 32;   // n
    const int by = blockIdx.y * 32;   // k
    const int tx = threadIdx.x, ty = threadIdx.y;
#pragma unroll
    for (int i = 0; i < 32; i += 8)
        t[ty + i][tx] = src[(size_t)(by + ty + i) * Nd + bx + tx];
    __syncthreads();
#pragma unroll
    for (int i = 0; i < 32; i += 8)
        dst[(size_t)(bx + ty + i) * Kd + by + tx] = tf32r(t[tx][ty + i]);
}

// ---------------------------------------------------------------------------
// tf32 GEMM: ldmatrix frags + 3-stage cp.async pipeline, 1 barrier/iter,
// 2 CTAs/SM. A [M][KD], Bt [N][KD] (pre-transposed), tf32-rounded.
// BM=BN=128, BK=16, 256 threads, warps 2m x 4n.
// ---------------------------------------------------------------------------
template<bool ROUND, bool HASBIAS>
__global__ __launch_bounds__(256, 2) void gemm_lm(
    const float* __restrict__ A,
    const float* __restrict__ Bt0, const float* __restrict__ Bt1,
    const float* __restrict__ bias0, const float* __restrict__ bias1,
    float* __restrict__ C0, float* __restrict__ C1, int N)
{
    constexpr int KD = 2048, BK = 16, ASS = 20;
    constexpr int NIT = KD / BK;

    __shared__ float As[3][128 * ASS];
    __shared__ float Bs[3][128 * ASS];

    const int tid = threadIdx.x;
    const int lane = tid & 31, w = tid >> 5;
    const int wm0 = (w & 1) * 64;
    const int wn0 = (w >> 1) * 32;
    const int bm = blockIdx.y * 128;
    const int bn = blockIdx.x * 128;

    const float* Bt  = (blockIdx.z == 0) ? Bt0 : Bt1;
    const float* bia = (blockIdx.z == 0) ? bias0 : bias1;
    float* C         = (blockIdx.z == 0) ? C0 : C1;

    const int cr = tid & 127;
    const int cc8 = (tid >> 7) * 8;
    const uint32_t sA = (uint32_t)__cvta_generic_to_shared(&As[0][0]);
    const uint32_t sB = (uint32_t)__cvta_generic_to_shared(&Bs[0][0]);

    const int g = lane >> 3, r = lane & 7;
    const int a_ro = (g & 1) * 8 + r, a_co = (g >> 1) * 4;
    const int b_ro = (g >> 1) * 8 + r, b_co = (g & 1) * 4;

    float acc[4][4][4];
#pragma unroll
    for (int mi = 0; mi < 4; mi++)
#pragma unroll
        for (int nj = 0; nj < 4; nj++)
#pragma unroll
            for (int c = 0; c < 4; c++) acc[mi][nj][c] = 0.0f;

    auto issue = [&](int st, int k0) {
        const float* ga = &A[(size_t)(bm + cr) * KD + k0 + cc8];
        uint32_t sa = sA + (uint32_t)((st * 128 + cr) * ASS + cc8) * 4u;
        cpa16(sa, ga); cpa16(sa + 16, ga + 4);
        const float* gb = &Bt[(size_t)(bn + cr) * KD + k0 + cc8];
        uint32_t sb = sB + (uint32_t)((st * 128 + cr) * ASS + cc8) * 4u;
        cpa16(sb, gb); cpa16(sb + 16, gb + 4);
    };

    issue(0, 0);       cp_commit();
    issue(1, BK);      cp_commit();

    int st = 0;
    for (int it = 0; it < NIT; it++) {
        if (it + 1 < NIT) cp_wait<1>(); else cp_wait<0>();
        __syncthreads();
        const uint32_t aB = sA + (uint32_t)(st * 128 * ASS) * 4u;
        const uint32_t bB = sB + (uint32_t)(st * 128 * ASS) * 4u;

        uint32_t af[2][4][4], bf[2][4][2];
#pragma unroll
        for (int ks = 0; ks < 2; ks++) {
            const int kk = ks * 8;
#pragma unroll
            for (int mi = 0; mi < 4; mi++) {
                uint32_t ad = aB + (uint32_t)(((wm0 + 16 * mi + a_ro) * ASS) + kk + a_co) * 4u;
                ldsm4(af[ks][mi][0], af[ks][mi][1], af[ks][mi][2], af[ks][mi][3], ad);
            }
#pragma unroll
            for (int p = 0; p < 2; p++) {
                uint32_t bd = bB + (uint32_t)(((wn0 + 16 * p + b_ro) * ASS) + kk + b_co) * 4u;
                ldsm4(bf[ks][2 * p][0], bf[ks][2 * p][1], bf[ks][2 * p + 1][0], bf[ks][2 * p + 1][1], bd);
            }
        }
#pragma unroll
        for (int ks = 0; ks < 2; ks++)
#pragma unroll
            for (int mi = 0; mi < 4; mi++)
#pragma unroll
                for (int nj = 0; nj < 4; nj++)
                    mma_tf32(acc[mi][nj], af[ks][mi], bf[ks][nj]);

        if (it + 2 < NIT) {
            int wst = (st + 2) % 3;
            issue(wst, (it + 2) * BK);
            cp_commit();
        }
        st = (st + 1) % 3;
    }

#pragma unroll
    for (int mi = 0; mi < 4; mi++) {
#pragma unroll
        for (int nj = 0; nj < 4; nj++) {
            int row = bm + wm0 + 16 * mi + (lane >> 2);
            int col = bn + wn0 + 8 * nj + 2 * (lane & 3);
            float bx = 0.0f, by = 0.0f;
            if (HASBIAS) { bx = bia[col]; by = bia[col + 1]; }
            float v0x = acc[mi][nj][0] + bx, v0y = acc[mi][nj][1] + by;
            float v1x = acc[mi][nj][2] + bx, v1y = acc[mi][nj][3] + by;
            if (ROUND) {
                v0x = tf32r(v0x); v0y = tf32r(v0y);
                v1x = tf32r(v1x); v1y = tf32r(v1y);
            }
            *(float2*)&C[(size_t)row * N + col] = make_float2(v0x, v0y);
            *(float2*)&C[(size_t)(row + 8) * N + col] = make_float2(v1x, v1y);
        }
    }
}

// ---------------------------------------------------------------------------
// Scores kernel: E = 2^(QK^T * scale * log2e) causal-masked, + per-128-block
// row-sum partials. Same 3-stage pipeline.
// ---------------------------------------------------------------------------
__global__ __launch_bounds__(256, 2) void scores_lm() {
    constexpr int ASS = 20, BK = 16;
    const int nb = blockIdx.x, mb = blockIdx.y, h = blockIdx.z;
    if (nb > mb) return;
    const int kvh = h >> 2;

    __shared__ float As[3][128 * ASS];
    __shared__ float Bs[3][128 * ASS];
    __shared__ float red[128 * 4];

    const int tid = threadIdx.x;
    const int lane = tid & 31, w = tid >> 5;
    const int wm0 = (w & 1) * 64;
    const int wn0 = (w >> 1) * 32;

    const int cr = tid & 127;
    const int cc8 = (tid >> 7) * 8;
    const uint32_t sA = (uint32_t)__cvta_generic_to_shared(&As[0][0]);
    const uint32_t sB = (uint32_t)__cvta_generic_to_shared(&Bs[0][0]);

    const int g = lane >> 3, r = lane & 7;
    const int a_ro = (g & 1) * 8 + r, a_co = (g >> 1) * 4;
    const int b_ro = (g >> 1) * 8 + r, b_co = (g & 1) * 4;

    const float* Qg = g_q + (size_t)(mb * 128) * DMODEL + h * HDIM;
    const float* Kg = g_k + (size_t)(nb * 128) * KV_DM + kvh * HDIM;

    float acc[4][4][4];
#pragma unroll
    for (int mi = 0; mi < 4; mi++)
#pragma unroll
        for (int nj = 0; nj < 4; nj++)
#pragma unroll
            for (int c = 0; c < 4; c++) acc[mi][nj][c] = 0.0f;

    auto issue = [&](int st, int k0) {
        const float* ga = &Qg[(size_t)cr * DMODEL + k0 + cc8];
        uint32_t sa = sA + (uint32_t)((st * 128 + cr) * ASS + cc8) * 4u;
        cpa16(sa, ga); cpa16(sa + 16, ga + 4);
        const float* gb = &Kg[(size_t)cr * KV_DM + k0 + cc8];
        uint32_t sb = sB + (uint32_t)((st * 128 + cr) * ASS + cc8) * 4u;
        cpa16(sb, gb); cpa16(sb + 16, gb + 4);
    };

    issue(0, 0);      cp_commit();
    issue(1, BK);     cp_commit();

    constexpr int NIT = HDIM / BK;
    int st = 0;
    for (int it = 0; it < NIT; it++) {
        if (it + 1 < NIT) cp_wait<1>(); else cp_wait<0>();
        __syncthreads();
        const uint32_t aB = sA + (uint32_t)(st * 128 * ASS) * 4u;
        const uint32_t bB = sB + (uint32_t)(st * 128 * ASS) * 4u;
        uint32_t af[2][4][4], bf[2][4][2];
#pragma unroll
        for (int ks = 0; ks < 2; ks++) {
            const int kk = ks * 8;
#pragma unroll
            for (int mi = 0; mi < 4; mi++) {
                uint32_t ad = aB + (uint32_t)(((wm0 + 16 * mi + a_ro) * ASS) + kk + a_co) * 4u;
                ldsm4(af[ks][mi][0], af[ks][mi][1], af[ks][mi][2], af[ks][mi][3], ad);
            }
#pragma unroll
            for (int p = 0; p < 2; p++) {
                uint32_t bd = bB + (uint32_t)(((wn0 + 16 * p + b_ro) * ASS) + kk + b_co) * 4u;
                ldsm4(bf[ks][2 * p][0], bf[ks][2 * p][1], bf[ks][2 * p + 1][0], bf[ks][2 * p + 1][1], bd);
            }
        }
#pragma unroll
        for (int ks = 0; ks < 2; ks++)
#pragma unroll
            for (int mi = 0; mi < 4; mi++)
#pragma unroll
                for (int nj = 0; nj < 4; nj++)
                    mma_tf32(acc[mi][nj], af[ks][mi], bf[ks][nj]);

        if (it + 2 < NIT) {
            int wst = (st + 2) % 3;
            issue(wst, (it + 2) * BK);
            cp_commit();
        }
        st = (st + 1) % 3;
    }

    const float SCL2 = 0.08838834764831845f * 1.4426950408889634f;
    float* Eh = g_E + (size_t)h * S_LEN * S_LEN;
    float rs[4][2];
#pragma unroll
    for (int mi = 0; mi < 4; mi++) { rs[mi][0] = 0.f; rs[mi][1] = 0.f; }

#pragma unroll
    for (int mi = 0; mi < 4; mi++) {
#pragma unroll
        for (int nj = 0; nj < 4; nj++) {
            int row = mb * 128 + wm0 + 16 * mi + (lane >> 2);
            int col = nb * 128 + wn0 + 8 * nj + 2 * (lane & 3);
            float e0 = (col     <= row)     ? ex2f(acc[mi][nj][0] * SCL2) : 0.f;
            float e1 = (col + 1 <= row)     ? ex2f(acc[mi][nj][1] * SCL2) : 0.f;
            float e2 = (col     <= row + 8) ? ex2f(acc[mi][nj][2] * SCL2) : 0.f;
            float e3 = (col + 1 <= row + 8) ? ex2f(acc[mi][nj][3] * SCL2) : 0.f;
            *(float2*)&Eh[(size_t)row * S_LEN + col] = make_float2(e0, e1);
            *(float2*)&Eh[(size_t)(row + 8) * S_LEN + col] = make_float2(e2, e3);
            rs[mi][0] += e0 + e1;
            rs[mi][1] += e2 + e3;
        }
    }
#pragma unroll
    for (int mi = 0; mi < 4; mi++)
#pragma unroll
        for (int hh = 0; hh < 2; hh++) {
            rs[mi][hh] += __shfl_xor_sync(0xFFFFFFFFu, rs[mi][hh], 1);
            rs[mi][hh] += __shfl_xor_sync(0xFFFFFFFFu, rs[mi][hh], 2);
        }
    if ((lane & 3) == 0) {
        int wg = w >> 1;
#pragma unroll
        for (int mi = 0; mi < 4; mi++) {
            red[(wm0 + 16 * mi + (lane >> 2)) * 4 + wg]     = rs[mi][0];
            red[(wm0 + 16 * mi + 8 + (lane >> 2)) * 4 + wg] = rs[mi][1];
        }
    }
    __syncthreads();
    if (tid < 128)
        g_lpart[((size_t)h * S_LEN + mb * 128 + tid) * 16 + nb] =
            red[tid * 4] + red[tid * 4 + 1] + red[tid * 4 + 2] + red[tid * 4 + 3];
}

// ---------------------------------------------------------------------------
// Attention over E: single pass. p = E * il -> smem, colsums + P@V.
// ---------------------------------------------------------------------------
#define SP_OFF   0
#define VS_OFF   8704
#define RED_OFF  17408
#define IL_OFF   17920
#define ATTN_SMEM ((17920 + 128) * 4)

__global__ __launch_bounds__(512, 1) void attn_pv() {
    extern __shared__ float smem[];
    float* sP  = smem + SP_OFF;     // [128][68]
    float* Vs  = smem + VS_OFF;     // [64][136]
    float* red = smem + RED_OFF;    // [512]
    float* il  = smem + IL_OFF;     // [128]

    const int qt = 15 - blockIdx.x;
    const int h  = blockIdx.y;
    const int kvh = h >> 2;
    const int qbase = qt * 128;
    const int tid = threadIdx.x;
    const int lane = tid & 31, w = tid >> 5;
    const int wm  = (w & 3) * 32;
    const int wn2 = (w >> 2) * 32;

    const int g = lane >> 3, r = lane & 7;
    const int a_ro = (g & 1) * 8 + r, a_co = (g >> 1) * 4;
    const uint32_t sPT = (uint32_t)__cvta_generic_to_shared(sP);

    const float* Eh = g_E + (size_t)h * S_LEN * S_LEN;

    if (tid < 128) {
        const float* lp = &g_lpart[((size_t)h * S_LEN + qbase + tid) * 16];
        float l = 0.0f;
        for (int nb = 0; nb <= qt; nb++) l += lp[nb];
        il[tid] = 1.0f / l;
    }
    __syncthreads();

    const int prow = tid >> 2;
    const int pcb = (tid & 3) * 16;
    const float myil = il[prow];

    float o[2][4][4];
#pragma unroll
    for (int mi = 0; mi < 2; mi++)
#pragma unroll
        for (int nj = 0; nj < 4; nj++)
#pragma unroll
            for (int c = 0; c < 4; c++) o[mi][nj][c] = 0.0f;

    const int nkt = 2 * qt + 2;
    for (int kt = 0; kt < nkt; kt++) {
        {
            const float* ep = &Eh[(size_t)(qbase + prow) * S_LEN + kt * 64 + pcb];
#pragma unroll
            for (int i = 0; i < 4; i++) {
                float4 v = *(const float4*)&ep[4 * i];
                v.x *= myil; v.y *= myil; v.z *= myil; v.w *= myil;
                *(float4*)&sP[prow * 68 + pcb + 4 * i] = v;
            }
            int vr = tid >> 3, vcb = (tid & 7) * 16;
            const float* vp = &g_v[(size_t)(kt * 64 + vr) * KV_DM + kvh * HDIM + vcb];
#pragma unroll
            for (int i = 0; i < 4; i++)
                *(float4*)&Vs[vr * 136 + vcb + 4 * i] = *(const float4*)&vp[4 * i];
        }
        __syncthreads();

        if (tid < 256) {
            int c = tid & 63, seg = tid >> 6;
            float cs = 0.0f;
#pragma unroll 8
            for (int q = 0; q < 32; q++) cs += sP[(seg * 32 + q) * 68 + c];
            red[c * 4 + seg] = cs;
        }

#pragma unroll
        for (int ks = 0; ks < 8; ks++) {
            const int kk = ks * 8;
            uint32_t af[2][4], bf[4][2];
#pragma unroll
            for (int mi = 0; mi < 2; mi++) {
                uint32_t ad = sPT + (uint32_t)(((wm + 16 * mi + a_ro) * 68) + kk + a_co) * 4u;
                ldsm4(af[mi][0], af[mi][1], af[mi][2], af[mi][3], ad);
            }
#pragma unroll
            for (int nj = 0; nj < 4; nj++) {
                int n0 = wn2 + 8 * nj + (lane >> 2);
                bf[nj][0] = __float_as_uint(Vs[(kk + (lane & 3)) * 136 + n0]);
                bf[nj][1] = __float_as_uint(Vs[(kk + 4 + (lane & 3)) * 136 + n0]);
            }
#pragma unroll
            for (int mi = 0; mi < 2; mi++)
#pragma unroll
                for (int nj = 0; nj < 4; nj++)
                    mma_tf32(o[mi][nj], af[mi], bf[nj]);
        }
        __syncthreads();
        if (tid < 64)
            g_colpart[((size_t)h * NQT16 + qt) * S_LEN + kt * 64 + tid] =
                red[tid * 4] + red[tid * 4 + 1] + red[tid * 4 + 2] + red[tid * 4 + 3];
    }

#pragma unroll
    for (int mi = 0; mi < 2; mi++)
#pragma unroll
        for (int nj = 0; nj < 4; nj++) {
            int row = qbase + wm + 16 * mi + (lane >> 2);
            int col = h * HDIM + wn2 + 8 * nj + 2 * (lane & 3);
            *(float2*)&g_ctx[(size_t)row * DMODEL + col] =
                make_float2(tf32r(o[mi][nj][0]), tf32r(o[mi][nj][1]));
            *(float2*)&g_ctx[(size_t)(row + 8) * DMODEL + col] =
                make_float2(tf32r(o[mi][nj][2]), tf32r(o[mi][nj][3]));
        }
}

// ---------------------------------------------------------------------------
// Heavy-hitter mask via bitonic sort (exact jax.lax.top_k tie semantics).
// ---------------------------------------------------------------------------
__global__ __launch_bounds__(1024) void topk_kernel(float* __restrict__ mask_out) {
    const int h = blockIdx.x;
    const int tid = threadIdx.x;
    __shared__ unsigned long long keys[2048];

    for (int i = tid; i < 2048; i += 1024) {
        unsigned ev = 0u;
        if (i < SEL) {
            float s = 0.0f;
#pragma unroll
            for (int qt = 0; qt < NQT16; qt++)
                s += g_colpart[((size_t)h * NQT16 + qt) * S_LEN + i];
            ev = encf(s);
        }
        keys[i] = ((unsigned long long)ev << 32) | (unsigned)(2047 - i);
    }
    float* mrow = mask_out + (size_t)h * MASKW;
    for (int i = tid; i < MASKW; i += 1024)
        mrow[i] = (i >= (MASKW - RECENT)) ? 1.0f : 0.0f;
    __syncthreads();

    for (int k = 2; k <= 2048; k <<= 1) {
        for (int j = k >> 1; j > 0; j >>= 1) {
            for (int idx = tid; idx < 2048; idx += 1024) {
                int ixj = idx ^ j;
                if (ixj > idx) {
                    unsigned long long a = keys[idx], b = keys[ixj];
                    bool up = (idx & k) == 0;
                    if (up ? (a > b) : (a < b)) { keys[idx] = b; keys[ixj] = a; }
                }
            }
            __syncthreads();
        }
    }
    for (int i = 2048 - HEAVY + tid; i < 2048; i += 1024) {
        int idx = 2047 - (int)(keys[i] & 0xFFFFFFFFu);
        mrow[idx] = 1.0f;
    }
}

// ---------------------------------------------------------------------------
extern "C" void kernel_launch(void* const* d_in, const int* in_sizes, int n_in,
                              void* d_out, int out_size) {
    (void)in_sizes; (void)n_in; (void)out_size;
    const float* hidden = (const float*)d_in[0];
    const float* q_w = (const float*)d_in[1];
    const float* q_b = (const float*)d_in[2];
    const float* k_w = (const float*)d_in[3];
    const float* k_b = (const float*)d_in[4];
    const float* v_w = (const float*)d_in[5];
    const float* v_b = (const float*)d_in[6];
    const float* o_w = (const float*)d_in[7];
    float* out = (float*)d_out;

    static bool init = false;
    static cudaStream_t sA, sB, sC;
    static cudaEvent_t evRoot, evHid, evKV, evZero, evAttn, evTrrO, evDoneA, evDoneC;
    if (!init) {
        cudaFuncSetAttribute(attn_pv, cudaFuncAttributeMaxDynamicSharedMemorySize, ATTN_SMEM);
        cudaStreamCreateWithFlags(&sA, cudaStreamNonBlocking);
        cudaStreamCreateWithFlags(&sB, cudaStreamNonBlocking);
        cudaStreamCreateWithFlags(&sC, cudaStreamNonBlocking);
        cudaEventCreateWithFlags(&evRoot, cudaEventDisableTiming);
        cudaEventCreateWithFlags(&evHid,  cudaEventDisableTiming);
        cudaEventCreateWithFlags(&evKV,   cudaEventDisableTiming);
        cudaEventCreateWithFlags(&evZero, cudaEventDisableTiming);
        cudaEventCreateWithFlags(&evAttn, cudaEventDisableTiming);
        cudaEventCreateWithFlags(&evTrrO, cudaEventDisableTiming);
        cudaEventCreateWithFlags(&evDoneA, cudaEventDisableTiming);
        cudaEventCreateWithFlags(&evDoneC, cudaEventDisableTiming);
        init = true;
    }

    float *ghid, *gqwT, *gkwT, *gvwT, *gowT, *gq, *gk, *gv, *gctx, *gcp;
    cudaGetSymbolAddress((void**)&ghid, g_hid);
    cudaGetSymbolAddress((void**)&gqwT, g_qwT);
    cudaGetSymbolAddress((void**)&gkwT, g_kwT);
    cudaGetSymbolAddress((void**)&gvwT, g_vwT);
    cudaGetSymbolAddress((void**)&gowT, g_owT);
    cudaGetSymbolAddress((void**)&gq,   g_q);
    cudaGetSymbolAddress((void**)&gk,   g_k);
    cudaGetSymbolAddress((void**)&gv,   g_v);
    cudaGetSymbolAddress((void**)&gctx, g_ctx);
    cudaGetSymbolAddress((void**)&gcp,  g_colpart);

    // fork from the capture (legacy) stream
    cudaEventRecord(evRoot, 0);
    cudaStreamWaitEvent(sA, evRoot, 0);
    cudaStreamWaitEvent(sB, evRoot, 0);
    cudaStreamWaitEvent(sC, evRoot, 0);

    dim3 tb(32, 8);
    // sA: round_hid -> trr_q -> gemmQ -> scores -> attn -> gemmO
    round4_kernel<<<(S_LEN * DMODEL / 4 + 255) / 256, 256, 0, sA>>>(
        (float4*)ghid, (const float4*)hidden, S_LEN * DMODEL / 4);
    cudaEventRecord(evHid, sA);
    trr_kernel<<<dim3(DMODEL / 32, DMODEL / 32), tb, 0, sA>>>(gqwT, q_w, DMODEL, DMODEL);
    // sB: trr_k -> trr_v -> (wait hid) -> gemmKV
    trr_kernel<<<dim3(KV_DM / 32, DMODEL / 32), tb, 0, sB>>>(gkwT, k_w, DMODEL, KV_DM);
    trr_kernel<<<dim3(KV_DM / 32, DMODEL / 32), tb, 0, sB>>>(gvwT, v_w, DMODEL, KV_DM);
    // sC: trr_o, zero
    trr_kernel<<<dim3(DMODEL / 32, DMODEL / 32), tb, 0, sC>>>(gowT, o_w, DMODEL, DMODEL);
    cudaEventRecord(evTrrO, sC);

    gemm_lm<true, true><<<dim3(DMODEL / 128, S_LEN / 128, 1), 256, 0, sA>>>(
        ghid, gqwT, nullptr, q_b, nullptr, gq, nullptr, DMODEL);

    cudaStreamWaitEvent(sB, evHid, 0);
    gemm_lm<true, true><<<dim3(KV_DM / 128, S_LEN / 128, 2), 256, 0, sB>>>(
        ghid, gkwT, gvwT, k_b, v_b, gk, gv, KV_DM);
    cudaEventRecord(evKV, sB);

    const int ncp = NH * NQT16 * S_LEN;
    zero_kernel<<<(ncp + 255) / 256, 256, 0, sC>>>(gcp, ncp);
    cudaEventRecord(evZero, sC);

    cudaStreamWaitEvent(sA, evKV, 0);
    scores_lm<<<dim3(16, 16, NH), 256, 0, sA>>>();

    cudaStreamWaitEvent(sA, evZero, 0);
    attn_pv<<<dim3(16, NH), 512, ATTN_SMEM, sA>>>();
    cudaEventRecord(evAttn, sA);

    // sC: topk (after attn), overlaps with gemmO on sA
    cudaStreamWaitEvent(sC, evAttn, 0);
    topk_kernel<<<NH, 1024, 0, sC>>>(out + (size_t)S_LEN * DMODEL);
    cudaEventRecord(evDoneC, sC);

    cudaStreamWaitEvent(sA, evTrrO, 0);
    gemm_lm<false, false><<<dim3(DMODEL / 128, S_LEN / 128, 1), 256, 0, sA>>>(
        gctx, gowT, nullptr, nullptr, nullptr, out, nullptr, DMODEL);
    cudaEventRecord(evDoneA, sA);

    // join back to the capture stream
    cudaStreamWaitEvent(0, evDoneA, 0);
    cudaStreamWaitEvent(0, evDoneC, 0);
}